// round 5
// baseline (speedup 1.0000x reference)
#include <cuda_runtime.h>
#include <math.h>
#include <stdint.h>

#define Bn 8
#define Tn 2048
#define Cn 768
#define Hn 12
#define KSEL 1024
#define DFF 3072
#define BT (Bn*Tn)      /* 16384 */
#define BKn (Bn*KSEL)   /* 8192 */
#define G3C (3*Cn)      /* 2304 */

typedef unsigned long long ull;

// ---------------- f32x2 packed helpers (FFMA2 path, sm_100+) ----------------
__device__ __forceinline__ ull pk2(float x, float y) {
    ull r; asm("mov.b64 %0, {%1, %2};" : "=l"(r) : "f"(x), "f"(y)); return r;
}
__device__ __forceinline__ ull dup2(float x) { return pk2(x, x); }
__device__ __forceinline__ void fma2(ull &acc, ull a, ull b) {
    asm("fma.rn.f32x2 %0, %1, %2, %0;" : "+l"(acc) : "l"(a), "l"(b));
}
__device__ __forceinline__ ull mul2(ull a, ull b) {
    ull r; asm("mul.rn.f32x2 %0, %1, %2;" : "=l"(r) : "l"(a), "l"(b)); return r;
}
__device__ __forceinline__ float2 upk2(ull v) {
    float2 r; asm("mov.b64 {%0, %1}, %2;" : "=f"(r.x), "=f"(r.y) : "l"(v)); return r;
}
__device__ __forceinline__ unsigned cvt_tf32(float x) {
    unsigned u; asm("cvt.rna.tf32.f32 %0, %1;" : "=r"(u) : "f"(x)); return u;
}

// ---------------- cp.async helpers ------------------------------------------
__device__ __forceinline__ uint32_t smem_u32(const void* p) {
    uint32_t a; asm("{ .reg .u64 t; cvta.to.shared.u64 t, %1; cvt.u32.u64 %0, t; }"
                    : "=r"(a) : "l"(p));
    return a;
}
__device__ __forceinline__ void cp16(uint32_t saddr, const void* gaddr) {
    asm volatile("cp.async.cg.shared.global [%0], [%1], 16;"
                 :: "r"(saddr), "l"(__cvta_generic_to_global(gaddr)));
}
__device__ __forceinline__ void cp_commit() { asm volatile("cp.async.commit_group;"); }
template<int N>
__device__ __forceinline__ void cp_waitg() {
    asm volatile("cp.async.wait_group %0;" :: "n"(N) : "memory");
}

// ---------------- scratch (device globals; no allocation allowed) ----------
__device__ float g_xi[(size_t)BT*G3C];
__device__ float g_hrnn[(size_t)BT*Cn];
__device__ float g_hstate[Bn*Cn];
__device__ float g_energy[BT];
__device__ int   g_idx[BKn];
__device__ int   g_selmap[BT];
__device__ float g_xsel[(size_t)BKn*Cn];
__device__ float g_gsel[BKn];
__device__ float g_qkv[(size_t)BKn*G3C];
__device__ float g_y[(size_t)BKn*Cn];
__device__ float g_weighted[(size_t)BKn*Cn];
__device__ float g_hln[(size_t)BT*Cn];
__device__ float g_mid[(size_t)BT*DFF];
__device__ unsigned g_bar;
__device__ int g_active;

// ---------------- init ------------------------------------------------------
__global__ void init_kernel() {
    int tid = blockIdx.x * blockDim.x + threadIdx.x;
    if (tid == 0) { g_bar = 0u; g_active = 0; }
    for (int i = tid; i < Bn*Cn; i += gridDim.x*blockDim.x) g_hstate[i] = 0.f;
    for (int i = tid; i < BT;    i += gridDim.x*blockDim.x) g_selmap[i] = -1;
}

// ============================================================================
// TF32 tensor-core GEMM (mma.sync): C[M,N] = A[M,K] @ W[N,K]^T + bias
// 128x128 CTA tile, 16-wide K tiles, double buffered, 2 CTAs/SM.
// EP: 0 none, 1 gelu(exact erf), 2 row-scale(extra[m]), 3 residual(extra[m*N+n])
// ============================================================================
template<int EP>
__global__ __launch_bounds__(256, 2)
void gemm_tc_kernel(const float* __restrict__ A, const float* __restrict__ W,
                    const float* __restrict__ bias, const float* __restrict__ extra,
                    float* __restrict__ Cc, int M, int N, int K) {
    __shared__ float Asm[2][2048];
    __shared__ float Wsm[2][2048];

    int tid = threadIdx.x;
    int m0 = blockIdx.y * 128, n0 = blockIdx.x * 128;
    int wid = tid >> 5, L = tid & 31;
    int warp_m = wid >> 2;        // 0..1 (64 rows each)
    int warp_n = wid & 3;         // 0..3 (32 cols each)
    int r = L >> 2, c4 = L & 3;
    int slot = 4*r + (c4 ^ (r & 3));   // swizzled lane slot for frag reads

    float cacc[4][4][4];
#pragma unroll
    for (int mt = 0; mt < 4; mt++)
#pragma unroll
        for (int nt = 0; nt < 4; nt++)
#pragma unroll
            for (int q = 0; q < 4; q++) cacc[mt][nt][q] = 0.f;

    int idxA0 = tid, idxA1 = tid + 256;

    // ---- prologue: tile 0 into buffer 0 ----
    {
#pragma unroll
        for (int it = 0; it < 2; it++) {
            int idx = (it == 0) ? idxA0 : idxA1;
            int m = idx >> 2, kq = idx & 3;
            float4 v = *(const float4*)(A + (size_t)(m0 + m) * K + kq*4);
            int sb = (((m>>4)*2 + (kq>>1))*32 + 4*(m&7));
            int comp = (kq&1)*2 + ((m>>3)&1);
            float vl[4] = {v.x, v.y, v.z, v.w};
#pragma unroll
            for (int e = 0; e < 4; e++)
                Asm[0][(sb + (e ^ (m&3)))*4 + comp] = __uint_as_float(cvt_tf32(vl[e]));

            int n = idx >> 2;
            float4 wv = *(const float4*)(W + (size_t)(n0 + n) * K + kq*4);
            int sbw = (((n>>3)*2 + (kq>>1))*32 + 4*(n&7));
            float wl[4] = {wv.x, wv.y, wv.z, wv.w};
#pragma unroll
            for (int e = 0; e < 4; e++)
                Wsm[0][(sbw + (e ^ (n&3)))*2 + (kq&1)] = __uint_as_float(cvt_tf32(wl[e]));
        }
    }
    __syncthreads();

    int buf = 0;
    for (int kt = 16; kt <= K; kt += 16) {
        bool more = (kt < K);
        float4 pvA[2], pvW[2];
        if (more) {
#pragma unroll
            for (int it = 0; it < 2; it++) {
                int idx = (it == 0) ? idxA0 : idxA1;
                int m = idx >> 2, kq = idx & 3;
                pvA[it] = *(const float4*)(A + (size_t)(m0 + m) * K + kt + kq*4);
                pvW[it] = *(const float4*)(W + (size_t)(n0 + m) * K + kt + kq*4);
            }
        }

        // ---- compute current buffer ----
#pragma unroll
        for (int s = 0; s < 2; s++) {
            float4 af[4]; float2 bf[4];
#pragma unroll
            for (int mt = 0; mt < 4; mt++)
                af[mt] = *(const float4*)&Asm[buf][((((warp_m*4 + mt)*2 + s)*32) + slot)*4];
#pragma unroll
            for (int nt = 0; nt < 4; nt++)
                bf[nt] = *(const float2*)&Wsm[buf][((((warp_n*4 + nt)*2 + s)*32) + slot)*2];
#pragma unroll
            for (int mt = 0; mt < 4; mt++) {
                unsigned a0 = __float_as_uint(af[mt].x), a1 = __float_as_uint(af[mt].y);
                unsigned a2 = __float_as_uint(af[mt].z), a3 = __float_as_uint(af[mt].w);
#pragma unroll
                for (int nt = 0; nt < 4; nt++) {
                    unsigned b0 = __float_as_uint(bf[nt].x), b1 = __float_as_uint(bf[nt].y);
                    asm volatile(
                        "mma.sync.aligned.m16n8k8.row.col.f32.tf32.tf32.f32 "
                        "{%0,%1,%2,%3}, {%4,%5,%6,%7}, {%8,%9}, {%0,%1,%2,%3};"
                        : "+f"(cacc[mt][nt][0]), "+f"(cacc[mt][nt][1]),
                          "+f"(cacc[mt][nt][2]), "+f"(cacc[mt][nt][3])
                        : "r"(a0), "r"(a1), "r"(a2), "r"(a3), "r"(b0), "r"(b1));
                }
            }
        }

        if (more) {
            int nb = buf ^ 1;
#pragma unroll
            for (int it = 0; it < 2; it++) {
                int idx = (it == 0) ? idxA0 : idxA1;
                int m = idx >> 2, kq = idx & 3;
                int sb = (((m>>4)*2 + (kq>>1))*32 + 4*(m&7));
                int comp = (kq&1)*2 + ((m>>3)&1);
                float vl[4] = {pvA[it].x, pvA[it].y, pvA[it].z, pvA[it].w};
#pragma unroll
                for (int e = 0; e < 4; e++)
                    Asm[nb][(sb + (e ^ (m&3)))*4 + comp] = __uint_as_float(cvt_tf32(vl[e]));
                int sbw = (((m>>3)*2 + (kq>>1))*32 + 4*(m&7));
                float wl[4] = {pvW[it].x, pvW[it].y, pvW[it].z, pvW[it].w};
#pragma unroll
                for (int e = 0; e < 4; e++)
                    Wsm[nb][(sbw + (e ^ (m&3)))*2 + (kq&1)] = __uint_as_float(cvt_tf32(wl[e]));
            }
        }
        __syncthreads();
        buf ^= 1;
    }

    // ---- epilogue ----
#pragma unroll
    for (int mt = 0; mt < 4; mt++) {
        int gm = m0 + warp_m*64 + mt*16 + r;
        float rs0 = (EP == 2) ? extra[gm] : 0.f;
        float rs1 = (EP == 2) ? extra[gm + 8] : 0.f;
#pragma unroll
        for (int nt = 0; nt < 4; nt++) {
            int gn = n0 + warp_n*32 + nt*8 + 2*c4;
            float b0 = bias[gn], b1 = bias[gn + 1];
#pragma unroll
            for (int half = 0; half < 2; half++) {
                int row = gm + half*8;
                float v0 = cacc[mt][nt][half*2 + 0] + b0;
                float v1 = cacc[mt][nt][half*2 + 1] + b1;
                if (EP == 1) {
                    v0 = 0.5f * v0 * (1.f + erff(v0 * 0.70710678118654752f));
                    v1 = 0.5f * v1 * (1.f + erff(v1 * 0.70710678118654752f));
                }
                if (EP == 2) { float rs = half ? rs1 : rs0; v0 *= rs; v1 *= rs; }
                if (EP == 3) {
                    v0 += extra[(size_t)row * N + gn];
                    v1 += extra[(size_t)row * N + gn + 1];
                }
                float2 o = make_float2(v0, v1);
                *(float2*)(Cc + (size_t)row * N + gn) = o;
            }
        }
    }
}

// ---------------- fp32 SGEMM (FFMA2) — used ONLY for xi (pre-selection) ------
__global__ __launch_bounds__(256, 2)
void gemm_kernel(const float* __restrict__ A, const float* __restrict__ W,
                 const float* __restrict__ bias, const float* __restrict__ extra,
                 float* __restrict__ Cc, int M, int N, int K) {
    __shared__ float As[2][8][128];
    __shared__ float Bs[2][8][128];
    int tid = threadIdx.x;
    int m0 = blockIdx.y * 128, n0 = blockIdx.x * 128;
    int tr = tid >> 4, tc = tid & 15;

    ull acc[8][4];
#pragma unroll
    for (int i = 0; i < 8; i++)
#pragma unroll
        for (int j = 0; j < 4; j++) acc[i][j] = 0ull;

    int lr = tid >> 1;
    int lc = (tid & 1) * 4;
    const float* Ap = A + (size_t)(m0 + lr) * K + lc;
    const float* Wp = W + (size_t)(n0 + lr) * K + lc;

    {
        float4 av = *(const float4*)(Ap);
        float4 wv = *(const float4*)(Wp);
        As[0][lc + 0][lr] = av.x; As[0][lc + 1][lr] = av.y;
        As[0][lc + 2][lr] = av.z; As[0][lc + 3][lr] = av.w;
        Bs[0][lc + 0][lr] = wv.x; Bs[0][lc + 1][lr] = wv.y;
        Bs[0][lc + 2][lr] = wv.z; Bs[0][lc + 3][lr] = wv.w;
    }
    __syncthreads();

    int buf = 0;
    for (int kt = 8; kt <= K; kt += 8) {
        float4 av, wv;
        bool more = (kt < K);
        if (more) {
            av = *(const float4*)(Ap + kt);
            wv = *(const float4*)(Wp + kt);
        }
#pragma unroll
        for (int kk = 0; kk < 8; kk++) {
            float4 a0 = *(const float4*)&As[buf][kk][tr*8];
            float4 a1 = *(const float4*)&As[buf][kk][tr*8 + 4];
            float4 b0 = *(const float4*)&Bs[buf][kk][tc*8];
            float4 b1 = *(const float4*)&Bs[buf][kk][tc*8 + 4];
            ull bp[4] = { pk2(b0.x,b0.y), pk2(b0.z,b0.w),
                          pk2(b1.x,b1.y), pk2(b1.z,b1.w) };
            ull ad[8] = { dup2(a0.x), dup2(a0.y), dup2(a0.z), dup2(a0.w),
                          dup2(a1.x), dup2(a1.y), dup2(a1.z), dup2(a1.w) };
#pragma unroll
            for (int i = 0; i < 8; i++)
#pragma unroll
                for (int jp = 0; jp < 4; jp++) fma2(acc[i][jp], ad[i], bp[jp]);
        }
        if (more) {
            int nb = buf ^ 1;
            As[nb][lc + 0][lr] = av.x; As[nb][lc + 1][lr] = av.y;
            As[nb][lc + 2][lr] = av.z; As[nb][lc + 3][lr] = av.w;
            Bs[nb][lc + 0][lr] = wv.x; Bs[nb][lc + 1][lr] = wv.y;
            Bs[nb][lc + 2][lr] = wv.z; Bs[nb][lc + 3][lr] = wv.w;
        }
        __syncthreads();
        buf ^= 1;
    }

#pragma unroll
    for (int i = 0; i < 8; i++) {
        int m = m0 + tr*8 + i;
#pragma unroll
        for (int jp = 0; jp < 4; jp++) {
            float2 p = upk2(acc[i][jp]);
            float vals[2] = { p.x, p.y };
#pragma unroll
            for (int h = 0; h < 2; h++) {
                int n = n0 + tc*8 + jp*2 + h;
                float v = vals[h] + bias[n];
                Cc[(size_t)m * N + n] = v;
            }
        }
    }
    (void)extra;
}

// ---------------- GRU persistent kernel -------------------------------------
// cp.async k-split pipelined h-broadcast + reduce-scatter lane reduction.
#define NCTA_GRU 128
#define CHB 6   /* channels per CTA: 128*6 = 768 */
__global__ __launch_bounds__(192, 1)
void gru_kernel(const float* __restrict__ xi, const float* __restrict__ Whh,
                const float* __restrict__ bhh) {
    __shared__ float hs[Bn][Cn];
    __shared__ float gbuf[CHB][3][Bn];
    int tid = threadIdx.x, w = tid >> 5, lane = tid & 31;
    int c0 = blockIdx.x * CHB;
    int ch = c0 + w;

    // recurrent weights resident in registers, packed as f32x2 pairs
    ull wp[3][6][2];
#pragma unroll
    for (int g = 0; g < 3; g++)
#pragma unroll
        for (int j = 0; j < 6; j++) {
            float4 v = __ldg((const float4*)(Whh + (size_t)(g*Cn + ch) * Cn) + (j*32 + lane));
            wp[g][j][0] = pk2(v.x, v.y);
            wp[g][j][1] = pk2(v.z, v.w);
        }

    bool is_comb = tid < (Bn * CHB);
    int bcomb = 0, ccomb = 0;
    float bhr = 0.f, bhz = 0.f, bhn = 0.f;
    if (is_comb) {
        bcomb = tid / CHB; ccomb = c0 + tid % CHB;
        bhr = __ldg(bhh + ccomb);
        bhz = __ldg(bhh + Cn + ccomb);
        bhn = __ldg(bhh + 2*Cn + ccomb);
    }

    // cp.async h-load assignment: 192 threads, 24 per batch, 4 f4 quads each
    int lb = tid / 24;                 // batch 0..7
    int lq = (tid % 24) * 4;           // f4 quad base within half (0..92)
    uint32_t hs_s = smem_u32(&hs[0][0]);
    const float* hp = g_hstate;

    unsigned target = NCTA_GRU;
    for (int t = 0; t < Tn; t++) {
        // phase 0: k quads 0..95 (j=0..2);  phase 1: 96..191 (j=3..5)
#pragma unroll
        for (int e = 0; e < 4; e++) {
            int q = lq + e;
            cp16(hs_s + lb*3072 + q*16, hp + (size_t)lb*Cn + q*4);
        }
        cp_commit();
#pragma unroll
        for (int e = 0; e < 4; e++) {
            int q = lq + 96 + e;
            cp16(hs_s + lb*3072 + q*16, hp + (size_t)lb*Cn + q*4);
        }
        cp_commit();

        float xr = 0.f, xz = 0.f, xn = 0.f;
        if (is_comb) {
            const float* xrow = xi + ((size_t)bcomb*Tn + t) * G3C + ccomb;
            xr = __ldg(xrow); xz = __ldg(xrow + Cn); xn = __ldg(xrow + 2*Cn);
        }

        ull acc2[3][Bn];
#pragma unroll
        for (int g = 0; g < 3; g++)
#pragma unroll
            for (int b = 0; b < Bn; b++) acc2[g][b] = 0ull;

        cp_waitg<1>();
        __syncthreads();
#pragma unroll
        for (int j = 0; j < 3; j++) {
            ull h01[Bn], h23[Bn];
#pragma unroll
            for (int b = 0; b < Bn; b++) {
                float4 h4 = ((const float4*)&hs[b][0])[j*32 + lane];
                h01[b] = pk2(h4.x, h4.y);
                h23[b] = pk2(h4.z, h4.w);
            }
#pragma unroll
            for (int b = 0; b < Bn; b++)
#pragma unroll
                for (int g = 0; g < 3; g++) {
                    fma2(acc2[g][b], wp[g][j][0], h01[b]);
                    fma2(acc2[g][b], wp[g][j][1], h23[b]);
                }
        }
        cp_waitg<0>();
        __syncthreads();
#pragma unroll
        for (int j = 3; j < 6; j++) {
            ull h01[Bn], h23[Bn];
#pragma unroll
            for (int b = 0; b < Bn; b++) {
                float4 h4 = ((const float4*)&hs[b][0])[j*32 + lane];
                h01[b] = pk2(h4.x, h4.y);
                h23[b] = pk2(h4.z, h4.w);
            }
#pragma unroll
            for (int b = 0; b < Bn; b++)
#pragma unroll
                for (int g = 0; g < 3; g++) {
                    fma2(acc2[g][b], wp[g][j][0], h01[b]);
                    fma2(acc2[g][b], wp[g][j][1], h23[b]);
                }
        }

        // ---- reduce-scatter lane reduction (36 shfl instead of 120) ----
        {
            float acc[24];
#pragma unroll
            for (int g = 0; g < 3; g++)
#pragma unroll
                for (int b = 0; b < Bn; b++) {
                    float2 p = upk2(acc2[g][b]);
                    acc[g*Bn + b] = p.x + p.y;
                }
            bool hi16 = (lane & 16) != 0;
            float v12[12];
#pragma unroll
            for (int i = 0; i < 12; i++) {
                float keep = hi16 ? acc[i + 12] : acc[i];
                float send = hi16 ? acc[i] : acc[i + 12];
                v12[i] = keep + __shfl_xor_sync(0xffffffffu, send, 16);
            }
            bool hi8 = (lane & 8) != 0;
            float v6[6];
#pragma unroll
            for (int i = 0; i < 6; i++) {
                float keep = hi8 ? v12[i + 6] : v12[i];
                float send = hi8 ? v12[i] : v12[i + 6];
                v6[i] = keep + __shfl_xor_sync(0xffffffffu, send, 8);
            }
#pragma unroll
            for (int i = 0; i < 6; i++) {
                v6[i] += __shfl_xor_sync(0xffffffffu, v6[i], 4);
                v6[i] += __shfl_xor_sync(0xffffffffu, v6[i], 2);
                v6[i] += __shfl_xor_sync(0xffffffffu, v6[i], 1);
            }
            if ((lane & 7) == 0) {
                int base = (hi16 ? 12 : 0) + (hi8 ? 6 : 0);
#pragma unroll
                for (int o = 0; o < 6; o++) {
                    int idx = base + o;
                    gbuf[w][idx >> 3][idx & 7] = v6[o];
                }
            }
        }
        __syncthreads();

        if (is_comb) {
            int cc = tid % CHB;
            float hr = gbuf[cc][0][bcomb] + bhr;
            float hz = gbuf[cc][1][bcomb] + bhz;
            float hn = gbuf[cc][2][bcomb] + bhn;
            float r = 1.f / (1.f + expf(-(xr + hr)));
            float z = 1.f / (1.f + expf(-(xz + hz)));
            float n = tanhf(xn + r * hn);
            float hold = hs[bcomb][ccomb];
            float hnew = (1.f - z) * n + z * hold;
            g_hstate[bcomb*Cn + ccomb] = hnew;
            g_hrnn[((size_t)bcomb*Tn + t) * Cn + ccomb] = hnew;
            __threadfence();
        }
        __syncthreads();
        if (tid == 0) {
            atomicAdd(&g_bar, 1u);
            volatile unsigned* p = &g_bar;
            while (*p < target) __nanosleep(32);
        }
        target += NCTA_GRU;
        __syncthreads();
    }
}

// ---------------- gate MLP / energy -----------------------------------------
__global__ __launch_bounds__(128)
void energy_kernel(const float* __restrict__ gw1, const float* __restrict__ gb1,
                   const float* __restrict__ gw2, const float* __restrict__ gb2,
                   float* __restrict__ out_energy) {
    int tok = blockIdx.x;
    int tid = threadIdx.x, w = tid >> 5, lane = tid & 31;
    __shared__ float dots[32];
    const float* h = g_hrnn + (size_t)tok * Cn;
#pragma unroll
    for (int jj = 0; jj < 8; jj++) {
        int j = w * 8 + jj;
        const float* wr = gw1 + (size_t)j * Cn;
        float p = 0.f;
        for (int k = lane; k < Cn; k += 32) p += h[k] * wr[k];
#pragma unroll
        for (int off = 16; off > 0; off >>= 1) p += __shfl_xor_sync(0xffffffffu, p, off);
        if (lane == 0) dots[j] = p;
    }
    __syncthreads();
    if (tid == 0) {
        float a = gb2[0];
#pragma unroll
        for (int j = 0; j < 32; j++) a += tanhf(dots[j] + gb1[j]) * gw2[j];
        float e = 1.f / (1.f + expf(-a));
        g_energy[tok] = e;
        out_energy[tok] = e;
        if (e > 0.5f) atomicAdd(&g_active, 1);
    }
}

// ---------------- exact top-k via bitonic sort -------------------------------
__global__ __launch_bounds__(1024)
void topk_kernel() {
    __shared__ unsigned long long keys[Tn];
    __shared__ int sel[KSEL];
    int b = blockIdx.x, tid = threadIdx.x;
    for (int e = tid; e < Tn; e += 1024) {
        unsigned u = __float_as_uint(g_energy[b*Tn + e]);
        u = (u & 0x80000000u) ? ~u : (u | 0x80000000u);
        keys[e] = ((unsigned long long)u << 32) | (unsigned)(Tn - 1 - e);
    }
    __syncthreads();
    for (int k = 2; k <= Tn; k <<= 1)
        for (int j = k >> 1; j > 0; j >>= 1) {
            int p = tid;
            int e = ((p & ~(j - 1)) << 1) | (p & (j - 1));
            int f = e | j;
            unsigned long long a = keys[e], c = keys[f];
            bool up = ((e & k) == 0);
            bool sw = up ? (a < c) : (a > c);
            if (sw) { keys[e] = c; keys[f] = a; }
            __syncthreads();
        }
    if (tid < KSEL) sel[tid] = Tn - 1 - (int)(keys[tid] & 0xffffffffull);
    __syncthreads();
    for (int k = 2; k <= KSEL; k <<= 1)
        for (int j = k >> 1; j > 0; j >>= 1) {
            if (tid < KSEL/2) {
                int p = tid;
                int e = ((p & ~(j - 1)) << 1) | (p & (j - 1));
                int f = e | j;
                int a = sel[e], c = sel[f];
                bool up = ((e & k) == 0);
                bool sw = up ? (a > c) : (a < c);
                if (sw) { sel[e] = c; sel[f] = a; }
            }
            __syncthreads();
        }
    if (tid < KSEL) g_idx[b*KSEL + tid] = sel[tid];
}

// ---------------- gather selected tokens -------------------------------------
__global__ __launch_bounds__(192)
void gather_kernel() {
    int bk = blockIdx.x;
    int b = bk / KSEL;
    int t = g_idx[bk];
    if (threadIdx.x == 0) {
        g_gsel[bk] = g_energy[b*Tn + t];
        g_selmap[b*Tn + t] = bk % KSEL;
    }
    const float4* src = (const float4*)(g_hrnn + ((size_t)b*Tn + t) * Cn);
    float4* dst = (float4*)(g_xsel + (size_t)bk * Cn);
    dst[threadIdx.x] = src[threadIdx.x];
}

// ---------------- flash attention (causal, hd=64, Klen=1024) -----------------
__global__ __launch_bounds__(256)
void attn_kernel() {
    extern __shared__ float sm[];
    float* Qs = sm;
    float* Ks = Qs + 64*65;
    float* Ps = Ks + 64*65;
    float* Vs = Ps + 64*65;
    int qt = blockIdx.x, bh = blockIdx.y;
    int b = bh / Hn, h = bh % Hn;
    int tid = threadIdx.x, tr = tid >> 4, tc = tid & 15;
    int q0 = qt * 64;
    const float* base = g_qkv + (size_t)b * KSEL * G3C;

    for (int i = tid; i < 1024; i += 256) {
        int r = i >> 4, d4 = i & 15;
        float4 v = __ldg((const float4*)(base + (size_t)(q0 + r)*G3C + h*64) + d4);
        Qs[r*65 + d4*4 + 0] = v.x; Qs[r*65 + d4*4 + 1] = v.y;
        Qs[r*65 + d4*4 + 2] = v.z; Qs[r*65 + d4*4 + 3] = v.w;
    }

    ull op[4][2];
    float m[4], l[4];
#pragma unroll
    for (int i = 0; i < 4; i++) {
        m[i] = -1e30f; l[i] = 0.f;
        op[i][0] = 0ull; op[i][1] = 0ull;
    }

    for (int kt = 0; kt <= qt; kt++) {
        int k0 = kt * 64;
        for (int i = tid; i < 1024; i += 256) {
            int c = i >> 4, d4 = i & 15;
            float4 kv = __ldg((const float4*)(base + (size_t)(k0 + c)*G3C + Cn + h*64) + d4);
            Ks[c*65 + d4*4 + 0] = kv.x; Ks[c*65 + d4*4 + 1] = kv.y;
            Ks[c*65 + d4*4 + 2] = kv.z; Ks[c*65 + d4*4 + 3] = kv.w;
            float4 vv = __ldg((const float4*)(base + (size_t)(k0 + c)*G3C + 2*Cn + h*64) + d4);
            ((float4*)(Vs + c*64))[d4] = vv;
        }
        __syncthreads();

        ull sp[4][2];
#pragma unroll
        for (int i = 0; i < 4; i++) { sp[i][0] = 0ull; sp[i][1] = 0ull; }
        for (int kk = 0; kk < 64; kk++) {
            ull ad[4], bp[2];
#pragma unroll
            for (int i = 0; i < 4; i++) ad[i] = dup2(Qs[(tr*4 + i)*65 + kk]);
            {
                float bb0 = Ks[(tc*4 + 0)*65 + kk];
                float bb1 = Ks[(tc*4 + 1)*65 + kk];
                float bb2 = Ks[(tc*4 + 2)*65 + kk];
                float bb3 = Ks[(tc*4 + 3)*65 + kk];
                bp[0] = pk2(bb0, bb1); bp[1] = pk2(bb2, bb3);
            }
#pragma unroll
            for (int i = 0; i < 4; i++) {
                fma2(sp[i][0], ad[i], bp[0]);
                fma2(sp[i][1], ad[i], bp[1]);
            }
        }
        float s[4][4];
#pragma unroll
        for (int i = 0; i < 4; i++) {
            float2 p0 = upk2(sp[i][0]), p1 = upk2(sp[i][1]);
            s[i][0] = p0.x * 0.125f; s[i][1] = p0.y * 0.125f;
            s[i][2] = p1.x * 0.125f; s[i][3] = p1.y * 0.125f;
        }
        if (kt == qt) {
#pragma unroll
            for (int i = 0; i < 4; i++)
#pragma unroll
                for (int j = 0; j < 4; j++)
                    if (k0 + tc*4 + j > q0 + tr*4 + i) s[i][j] = -1e30f;
        }
#pragma unroll
        for (int i = 0; i < 4; i++) {
            float rm = s[i][0];
#pragma unroll
            for (int j = 1; j < 4; j++) rm = fmaxf(rm, s[i][j]);
#pragma unroll
            for (int off = 8; off > 0; off >>= 1)
                rm = fmaxf(rm, __shfl_xor_sync(0xffffffffu, rm, off));
            float mn = fmaxf(m[i], rm);
            float alpha = expf(m[i] - mn);
            float rs = 0.f;
#pragma unroll
            for (int j = 0; j < 4; j++) {
                s[i][j] = expf(s[i][j] - mn);
                rs += s[i][j];
            }
#pragma unroll
            for (int off = 8; off > 0; off >>= 1)
                rs += __shfl_xor_sync(0xffffffffu, rs, off);
            l[i] = l[i] * alpha + rs;
            m[i] = mn;
            ull da = dup2(alpha);
            op[i][0] = mul2(op[i][0], da);
            op[i][1] = mul2(op[i][1], da);
#pragma unroll
            for (int j = 0; j < 4; j++) Ps[(tr*4 + i)*65 + tc*4 + j] = s[i][j];
        }
        __syncthreads();
        for (int c = 0; c < 64; c++) {
            ull pd[4], vp[2];
#pragma unroll
            for (int i = 0; i < 4; i++) pd[i] = dup2(Ps[(tr*4 + i)*65 + c]);
            {
                float4 vv = *(const float4*)(Vs + c*64 + tc*4);
                vp[0] = pk2(vv.x, vv.y); vp[1] = pk2(vv.z, vv.w);
            }
#pragma unroll
            for (int i = 0; i < 4; i++) {
                fma2(op[i][0], pd[i], vp[0]);
                fma2(op[i][1], pd[i], vp[1]);
            }
        }
        __syncthreads();
    }
#pragma unroll
    for (int i = 0; i < 4; i++) {
        float inv = 1.f / l[i];
        int row = b * KSEL + q0 + tr*4 + i;
        float2 p0 = upk2(op[i][0]), p1 = upk2(op[i][1]);
        float* dst = g_y + (size_t)row * Cn + h*64 + tc*4;
        dst[0] = p0.x * inv; dst[1] = p0.y * inv;
        dst[2] = p1.x * inv; dst[3] = p1.y * inv;
    }
}

// ---------------- LayerNorm with fused scatter-add ---------------------------
__global__ __launch_bounds__(256)
void ln_kernel(const float* __restrict__ g, const float* __restrict__ bb) {
    __shared__ float xrow[Cn];
    __shared__ float rbuf[16];
    int tok = blockIdx.x, tid = threadIdx.x;
    int b = tok >> 11;
    int sel = g_selmap[tok];
    float s = 0.f, s2 = 0.f;
    for (int c = tid; c < Cn; c += 256) {
        float v = g_hrnn[(size_t)tok*Cn + c];
        if (sel >= 0) v += g_weighted[((size_t)(b*KSEL + sel))*Cn + c];
        xrow[c] = v; s += v; s2 += v*v;
    }
#pragma unroll
    for (int off = 16; off > 0; off >>= 1) {
        s  += __shfl_xor_sync(0xffffffffu, s, off);
        s2 += __shfl_xor_sync(0xffffffffu, s2, off);
    }
    int w = tid >> 5;
    if ((tid & 31) == 0) { rbuf[w] = s; rbuf[8 + w] = s2; }
    __syncthreads();
    if (tid == 0) {
        float S = 0.f, S2 = 0.f;
        for (int i = 0; i < 8; i++) { S += rbuf[i]; S2 += rbuf[8 + i]; }
        float mu = S / (float)Cn;
        float var = S2 / (float)Cn - mu*mu;
        rbuf[0] = mu; rbuf[1] = rsqrtf(var + 1e-5f);
    }
    __syncthreads();
    float mu = rbuf[0], inv = rbuf[1];
    for (int c = tid; c < Cn; c += 256)
        g_hln[(size_t)tok*Cn + c] = (xrow[c] - mu) * inv * g[c] + bb[c];
}

// ---------------- finalize ----------------------------------------------------
__global__ void finalize_kernel(float* out) {
    out[(size_t)BT*Cn + BT] = (float)g_active;
}

// ---------------- launcher ----------------------------------------------------
extern "C" void kernel_launch(void* const* d_in, const int* in_sizes, int n_in,
                              void* d_out, int out_size) {
    const float* x      = (const float*)d_in[0];
    const float* W_ih   = (const float*)d_in[1];
    const float* W_hh   = (const float*)d_in[2];
    const float* b_ih   = (const float*)d_in[3];
    const float* b_hh   = (const float*)d_in[4];
    const float* gate_w1= (const float*)d_in[5];
    const float* gate_b1= (const float*)d_in[6];
    const float* gate_w2= (const float*)d_in[7];
    const float* gate_b2= (const float*)d_in[8];
    const float* qkv_w  = (const float*)d_in[9];
    const float* qkv_b  = (const float*)d_in[10];
    const float* proj_w = (const float*)d_in[11];
    const float* proj_b = (const float*)d_in[12];
    const float* ln_g   = (const float*)d_in[13];
    const float* ln_b   = (const float*)d_in[14];
    const float* ffn_w1 = (const float*)d_in[15];
    const float* ffn_b1 = (const float*)d_in[16];
    const float* ffn_w2 = (const float*)d_in[17];
    const float* ffn_b2 = (const float*)d_in[18];
    float* out = (float*)d_out;

    float *p_xi, *p_xsel, *p_qkv, *p_y, *p_weighted, *p_hln, *p_mid, *p_energy_out;
    cudaGetSymbolAddress((void**)&p_xi,       g_xi);
    cudaGetSymbolAddress((void**)&p_xsel,     g_xsel);
    cudaGetSymbolAddress((void**)&p_qkv,      g_qkv);
    cudaGetSymbolAddress((void**)&p_y,        g_y);
    cudaGetSymbolAddress((void**)&p_weighted, g_weighted);
    cudaGetSymbolAddress((void**)&p_hln,      g_hln);
    cudaGetSymbolAddress((void**)&p_mid,      g_mid);
    float* p_gsel; cudaGetSymbolAddress((void**)&p_gsel, g_gsel);
    p_energy_out = out + (size_t)BT*Cn;

    const int ATTN_SMEM = (3*64*65 + 64*64) * 4;
    cudaFuncSetAttribute(attn_kernel, cudaFuncAttributeMaxDynamicSharedMemorySize, ATTN_SMEM);

    // 0) init scratch state
    init_kernel<<<64, 256>>>();

    // 1) xi = x @ W_ih^T + b_ih   (fp32 FFMA2 — precision-critical path)
    gemm_kernel<<<dim3(G3C/128, BT/128), 256>>>(x, W_ih, b_ih, nullptr, p_xi, BT, G3C, Cn);

    // 2) GRU scan (persistent, global barrier per step)
    gru_kernel<<<NCTA_GRU, 192>>>(p_xi, W_hh, b_hh);

    // 3) gate MLP energy
    energy_kernel<<<BT, 128>>>(gate_w1, gate_b1, gate_w2, gate_b2, p_energy_out);

    // 4) exact top-k + ascending index sort
    topk_kernel<<<Bn, 1024>>>();

    // 5) gather selected tokens
    gather_kernel<<<BKn, 192>>>();

    // 6) qkv = x_sel @ qkv_w^T + qkv_b  (TF32 mma.sync)
    gemm_tc_kernel<0><<<dim3(G3C/128, BKn/128), 256>>>(p_xsel, qkv_w, qkv_b, nullptr, p_qkv, BKn, G3C, Cn);

    // 7) causal flash attention
    attn_kernel<<<dim3(KSEL/64, Bn*Hn), 256, ATTN_SMEM>>>();

    // 8) weighted = (y @ proj_w^T + proj_b) * g_sel  (TF32)
    gemm_tc_kernel<2><<<dim3(Cn/128, BKn/128), 256>>>(p_y, proj_w, proj_b, p_gsel, p_weighted, BKn, Cn, Cn);

    // 9) LayerNorm(h_rnn + scatter(weighted))
    ln_kernel<<<BT, 256>>>(ln_g, ln_b);

    // 10) mid = gelu(h_ln @ ffn_w1^T + ffn_b1)  (TF32)
    gemm_tc_kernel<1><<<dim3(DFF/128, BT/128), 256>>>(p_hln, ffn_w1, ffn_b1, nullptr, p_mid, BT, DFF, Cn);

    // 11) out_h = h_ln + mid @ ffn_w2^T + ffn_b2  (TF32) -> d_out
    gemm_tc_kernel<3><<<dim3(Cn/128, BT/128), 256>>>(p_mid, ffn_w2, ffn_b2, p_hln, out, BT, Cn, DFF);

    // 12) active count
    finalize_kernel<<<1, 1>>>(out);

    (void)in_sizes; (void)n_in; (void)out_size;
}

// round 6
// speedup vs baseline: 1.0897x; 1.0897x over previous
#include <cuda_runtime.h>
#include <math.h>
#include <stdint.h>

#define Bn 8
#define Tn 2048
#define Cn 768
#define Hn 12
#define KSEL 1024
#define DFF 3072
#define BT (Bn*Tn)      /* 16384 */
#define BKn (Bn*KSEL)   /* 8192 */
#define G3C (3*Cn)      /* 2304 */

typedef unsigned long long ull;

// ---------------- f32x2 packed helpers --------------------------------------
__device__ __forceinline__ ull pk2(float x, float y) {
    ull r; asm("mov.b64 %0, {%1, %2};" : "=l"(r) : "f"(x), "f"(y)); return r;
}
__device__ __forceinline__ ull dup2(float x) { return pk2(x, x); }
__device__ __forceinline__ void fma2(ull &acc, ull a, ull b) {
    asm("fma.rn.f32x2 %0, %1, %2, %0;" : "+l"(acc) : "l"(a), "l"(b));
}
__device__ __forceinline__ ull mul2(ull a, ull b) {
    ull r; asm("mul.rn.f32x2 %0, %1, %2;" : "=l"(r) : "l"(a), "l"(b)); return r;
}
__device__ __forceinline__ float2 upk2(ull v) {
    float2 r; asm("mov.b64 {%0, %1}, %2;" : "=f"(r.x), "=f"(r.y) : "l"(v)); return r;
}
__device__ __forceinline__ float rna_tf32(float x) {
    unsigned u; asm("cvt.rna.tf32.f32 %0, %1;" : "=r"(u) : "f"(x));
    return __uint_as_float(u);
}

// ---------------- cp.async helpers ------------------------------------------
__device__ __forceinline__ uint32_t smem_u32(const void* p) {
    uint32_t a; asm("{ .reg .u64 t; cvta.to.shared.u64 t, %1; cvt.u32.u64 %0, t; }"
                    : "=r"(a) : "l"(p));
    return a;
}
__device__ __forceinline__ void cp16(uint32_t saddr, const void* gaddr) {
    asm volatile("cp.async.cg.shared.global [%0], [%1], 16;"
                 :: "r"(saddr), "l"(__cvta_generic_to_global(gaddr)));
}
__device__ __forceinline__ void cp_commit() { asm volatile("cp.async.commit_group;"); }
template<int N>
__device__ __forceinline__ void cp_waitg() {
    asm volatile("cp.async.wait_group %0;" :: "n"(N) : "memory");
}

// ---------------- scratch -----------------------------------------------------
__device__ float g_xi[(size_t)BT*G3C];     // xi; later reused for rounded hln
__device__ float g_hrnn[(size_t)BT*Cn];
__device__ float g_hstate[Bn*Cn];
__device__ float g_energy[BT];
__device__ int   g_idx[BKn];
__device__ int   g_selmap[BT];
__device__ float g_xsel[(size_t)BKn*Cn];
__device__ float g_gsel[BKn];
__device__ float g_qkv[(size_t)BKn*G3C];
__device__ float g_y[(size_t)BKn*Cn];
__device__ float g_weighted[(size_t)BKn*Cn];
__device__ float g_hln[(size_t)BT*Cn];
__device__ float g_mid[(size_t)BT*DFF];
__device__ float g_wscr[7077888];          // rounded weights: qkv|proj|ffn1|ffn2
__device__ unsigned g_bar;
__device__ int g_active;

#define WOFF_QKV  0
#define WOFF_PROJ 1769472
#define WOFF_FFN1 2359296
#define WOFF_FFN2 4718592
#define WTOTAL    7077888

// ---------------- init --------------------------------------------------------
__global__ void init_kernel() {
    int tid = blockIdx.x * blockDim.x + threadIdx.x;
    if (tid == 0) { g_bar = 0u; g_active = 0; }
    for (int i = tid; i < Bn*Cn; i += gridDim.x*blockDim.x) g_hstate[i] = 0.f;
    for (int i = tid; i < BT;    i += gridDim.x*blockDim.x) g_selmap[i] = -1;
}

// ---------------- weight rounding (rna -> tf32 bit pattern) -------------------
__global__ __launch_bounds__(256)
void cvtw_kernel(const float* __restrict__ qkvw, const float* __restrict__ projw,
                 const float* __restrict__ w1, const float* __restrict__ w2) {
    int i = blockIdx.x * 256 + threadIdx.x;
    if (i >= WTOTAL) return;
    float v;
    if (i < WOFF_PROJ)       v = qkvw[i - WOFF_QKV];
    else if (i < WOFF_FFN1)  v = projw[i - WOFF_PROJ];
    else if (i < WOFF_FFN2)  v = w1[i - WOFF_FFN1];
    else                     v = w2[i - WOFF_FFN2];
    g_wscr[i] = rna_tf32(v);
}

// ============================================================================
// TF32 tensor-core GEMM (mma.sync, cp.async-fed): C[M,N] = A[M,K]@W[N,K]^T + bias
// Inputs A and W must already be tf32-rounded (low 13 mantissa bits zero).
// 128x128 CTA tile, k-tile 32, double-buffered cp.async, XOR-swizzled SMEM.
// EP: 0 none, 1 gelu(exact erf, store rounded), 2 row-scale, 3 residual
// ============================================================================
#define GSM_BYTES 65536   /* 2 stages x (A 16KB + W 16KB) */

template<int EP>
__global__ __launch_bounds__(256)
void gemm_tc_kernel(const float* __restrict__ A, const float* __restrict__ W,
                    const float* __restrict__ bias, const float* __restrict__ extra,
                    float* __restrict__ Cc, int M, int N, int K) {
    extern __shared__ float smdyn[];
    uint32_t sbase = smem_u32(smdyn);
    int tid = threadIdx.x;
    int m0 = blockIdx.y * 128, n0 = blockIdx.x * 128;
    int wid = tid >> 5, L = tid & 31;
    int warp_m = wid >> 2;        // 0..1 (64 rows)
    int warp_n = wid & 3;         // 0..3 (32 cols)
    int r = L >> 2, c4 = L & 3;

    float cacc[4][4][4];
#pragma unroll
    for (int mt = 0; mt < 4; mt++)
#pragma unroll
        for (int nt = 0; nt < 4; nt++)
#pragma unroll
            for (int q = 0; q < 4; q++) cacc[mt][nt][q] = 0.f;

    // stage layout (floats): [b*8192 + 0 : A 4096][b*8192 + 4096 : W 4096]
    // swizzled store/load: elem(row,k) at row*32 + ((k>>2 ^ (row&7))<<2) + (k&3)
    auto load_tile = [&](int c, int b) {
        const float* Ag = A + (size_t)m0 * K + c * 32;
        const float* Wg = W + (size_t)n0 * K + c * 32;
        uint32_t ab = sbase + b * 32768;
        uint32_t wb = ab + 16384;
#pragma unroll
        for (int i = 0; i < 4; i++) {
            int idx = tid + 256 * i;          // 0..1023
            int row = idx >> 3, g = idx & 7;
            uint32_t so = row * 128 + ((g ^ (row & 7)) << 4);
            cp16(ab + so, Ag + (size_t)row * K + g * 4);
            cp16(wb + so, Wg + (size_t)row * K + g * 4);
        }
        cp_commit();
    };

    load_tile(0, 0);
    const int NC = K >> 5;

    for (int c = 0; c < NC; c++) {
        if (c + 1 < NC) { load_tile(c + 1, (c + 1) & 1); cp_waitg<1>(); }
        else            { cp_waitg<0>(); }
        __syncthreads();

        const float* As = smdyn + (c & 1) * 8192;
        const float* Ws = As + 4096;
#pragma unroll
        for (int s = 0; s < 4; s++) {
            int g0 = 2 * s, g1 = 2 * s + 1;
            unsigned a[4][4];
#pragma unroll
            for (int mt = 0; mt < 4; mt++) {
                int r0 = warp_m * 64 + mt * 16 + r, r1 = r0 + 8;
                a[mt][0] = __float_as_uint(As[r0*32 + ((g0 ^ r) << 2) + c4]);
                a[mt][1] = __float_as_uint(As[r1*32 + ((g0 ^ r) << 2) + c4]);
                a[mt][2] = __float_as_uint(As[r0*32 + ((g1 ^ r) << 2) + c4]);
                a[mt][3] = __float_as_uint(As[r1*32 + ((g1 ^ r) << 2) + c4]);
            }
            unsigned bq[4][2];
#pragma unroll
            for (int nt = 0; nt < 4; nt++) {
                int nn = warp_n * 32 + nt * 8 + r;
                bq[nt][0] = __float_as_uint(Ws[nn*32 + ((g0 ^ r) << 2) + c4]);
                bq[nt][1] = __float_as_uint(Ws[nn*32 + ((g1 ^ r) << 2) + c4]);
            }
#pragma unroll
            for (int mt = 0; mt < 4; mt++)
#pragma unroll
                for (int nt = 0; nt < 4; nt++) {
                    asm volatile(
                        "mma.sync.aligned.m16n8k8.row.col.f32.tf32.tf32.f32 "
                        "{%0,%1,%2,%3}, {%4,%5,%6,%7}, {%8,%9}, {%0,%1,%2,%3};"
                        : "+f"(cacc[mt][nt][0]), "+f"(cacc[mt][nt][1]),
                          "+f"(cacc[mt][nt][2]), "+f"(cacc[mt][nt][3])
                        : "r"(a[mt][0]), "r"(a[mt][1]), "r"(a[mt][2]), "r"(a[mt][3]),
                          "r"(bq[nt][0]), "r"(bq[nt][1]));
                }
        }
        __syncthreads();
    }

    // ---- epilogue (fragment layout: row=lane>>2(+8), col=2*(lane&3)(+1)) ----
#pragma unroll
    for (int mt = 0; mt < 4; mt++) {
        int gm = m0 + warp_m*64 + mt*16 + r;
        float rs0 = (EP == 2) ? extra[gm] : 0.f;
        float rs1 = (EP == 2) ? extra[gm + 8] : 0.f;
#pragma unroll
        for (int nt = 0; nt < 4; nt++) {
            int gn = n0 + warp_n*32 + nt*8 + 2*c4;
            float b0 = bias[gn], b1 = bias[gn + 1];
#pragma unroll
            for (int half = 0; half < 2; half++) {
                int row = gm + half*8;
                float v0 = cacc[mt][nt][half*2 + 0] + b0;
                float v1 = cacc[mt][nt][half*2 + 1] + b1;
                if (EP == 1) {
                    v0 = 0.5f * v0 * (1.f + erff(v0 * 0.70710678118654752f));
                    v1 = 0.5f * v1 * (1.f + erff(v1 * 0.70710678118654752f));
                    v0 = rna_tf32(v0);   // mid feeds only ffn2 (tf32 GEMM)
                    v1 = rna_tf32(v1);
                }
                if (EP == 2) { float rs = half ? rs1 : rs0; v0 *= rs; v1 *= rs; }
                if (EP == 3) {
                    v0 += extra[(size_t)row * N + gn];
                    v1 += extra[(size_t)row * N + gn + 1];
                }
                *(float2*)(Cc + (size_t)row * N + gn) = make_float2(v0, v1);
            }
        }
    }
}

// ---------------- fp32 SGEMM (FFMA2) — xi only (pre-selection) ----------------
__global__ __launch_bounds__(256, 2)
void gemm_kernel(const float* __restrict__ A, const float* __restrict__ W,
                 const float* __restrict__ bias,
                 float* __restrict__ Cc, int M, int N, int K) {
    __shared__ float As[2][8][128];
    __shared__ float Bs[2][8][128];
    int tid = threadIdx.x;
    int m0 = blockIdx.y * 128, n0 = blockIdx.x * 128;
    int tr = tid >> 4, tc = tid & 15;

    ull acc[8][4];
#pragma unroll
    for (int i = 0; i < 8; i++)
#pragma unroll
        for (int j = 0; j < 4; j++) acc[i][j] = 0ull;

    int lr = tid >> 1;
    int lc = (tid & 1) * 4;
    const float* Ap = A + (size_t)(m0 + lr) * K + lc;
    const float* Wp = W + (size_t)(n0 + lr) * K + lc;

    {
        float4 av = *(const float4*)(Ap);
        float4 wv = *(const float4*)(Wp);
        As[0][lc + 0][lr] = av.x; As[0][lc + 1][lr] = av.y;
        As[0][lc + 2][lr] = av.z; As[0][lc + 3][lr] = av.w;
        Bs[0][lc + 0][lr] = wv.x; Bs[0][lc + 1][lr] = wv.y;
        Bs[0][lc + 2][lr] = wv.z; Bs[0][lc + 3][lr] = wv.w;
    }
    __syncthreads();

    int buf = 0;
    for (int kt = 8; kt <= K; kt += 8) {
        float4 av, wv;
        bool more = (kt < K);
        if (more) {
            av = *(const float4*)(Ap + kt);
            wv = *(const float4*)(Wp + kt);
        }
#pragma unroll
        for (int kk = 0; kk < 8; kk++) {
            float4 a0 = *(const float4*)&As[buf][kk][tr*8];
            float4 a1 = *(const float4*)&As[buf][kk][tr*8 + 4];
            float4 b0 = *(const float4*)&Bs[buf][kk][tc*8];
            float4 b1 = *(const float4*)&Bs[buf][kk][tc*8 + 4];
            ull bp[4] = { pk2(b0.x,b0.y), pk2(b0.z,b0.w),
                          pk2(b1.x,b1.y), pk2(b1.z,b1.w) };
            ull ad[8] = { dup2(a0.x), dup2(a0.y), dup2(a0.z), dup2(a0.w),
                          dup2(a1.x), dup2(a1.y), dup2(a1.z), dup2(a1.w) };
#pragma unroll
            for (int i = 0; i < 8; i++)
#pragma unroll
                for (int jp = 0; jp < 4; jp++) fma2(acc[i][jp], ad[i], bp[jp]);
        }
        if (more) {
            int nb = buf ^ 1;
            As[nb][lc + 0][lr] = av.x; As[nb][lc + 1][lr] = av.y;
            As[nb][lc + 2][lr] = av.z; As[nb][lc + 3][lr] = av.w;
            Bs[nb][lc + 0][lr] = wv.x; Bs[nb][lc + 1][lr] = wv.y;
            Bs[nb][lc + 2][lr] = wv.z; Bs[nb][lc + 3][lr] = wv.w;
        }
        __syncthreads();
        buf ^= 1;
    }

#pragma unroll
    for (int i = 0; i < 8; i++) {
        int m = m0 + tr*8 + i;
#pragma unroll
        for (int jp = 0; jp < 4; jp++) {
            float2 p = upk2(acc[i][jp]);
            float vals[2] = { p.x, p.y };
#pragma unroll
            for (int h = 0; h < 2; h++) {
                int n = n0 + tc*8 + jp*2 + h;
                Cc[(size_t)m * N + n] = vals[h] + bias[n];
            }
        }
    }
}

// ---------------- GRU persistent kernel (R3-proven version) -------------------
#define NCTA_GRU 128
#define CHB 6
__global__ __launch_bounds__(192, 1)
void gru_kernel(const float* __restrict__ xi, const float* __restrict__ Whh,
                const float* __restrict__ bhh) {
    __shared__ float hs[Bn][Cn];
    __shared__ float gbuf[CHB][3][Bn];
    int tid = threadIdx.x, w = tid >> 5, lane = tid & 31;
    int c0 = blockIdx.x * CHB;
    int ch = c0 + w;

    ull wp[3][6][2];
#pragma unroll
    for (int g = 0; g < 3; g++)
#pragma unroll
        for (int j = 0; j < 6; j++) {
            float4 v = __ldg((const float4*)(Whh + (size_t)(g*Cn + ch) * Cn) + (j*32 + lane));
            wp[g][j][0] = pk2(v.x, v.y);
            wp[g][j][1] = pk2(v.z, v.w);
        }

    bool is_comb = tid < (Bn * CHB);
    int bcomb = 0, ccomb = 0;
    float bhr = 0.f, bhz = 0.f, bhn = 0.f;
    if (is_comb) {
        bcomb = tid / CHB; ccomb = c0 + tid % CHB;
        bhr = __ldg(bhh + ccomb);
        bhz = __ldg(bhh + Cn + ccomb);
        bhn = __ldg(bhh + 2*Cn + ccomb);
    }

    unsigned target = NCTA_GRU;
    for (int t = 0; t < Tn; t++) {
        const float4* hp = (const float4*)g_hstate;
        float4* hd = (float4*)&hs[0][0];
#pragma unroll
        for (int i = 0; i < 8; i++) hd[tid + i*192] = __ldcg(hp + tid + i*192);

        float xr = 0.f, xz = 0.f, xn = 0.f;
        if (is_comb) {
            const float* xrow = xi + ((size_t)bcomb*Tn + t) * G3C + ccomb;
            xr = __ldg(xrow); xz = __ldg(xrow + Cn); xn = __ldg(xrow + 2*Cn);
        }
        __syncthreads();

        ull acc2[3][Bn];
#pragma unroll
        for (int g = 0; g < 3; g++)
#pragma unroll
            for (int b = 0; b < Bn; b++) acc2[g][b] = 0ull;

#pragma unroll
        for (int j = 0; j < 6; j++) {
            ull h01[Bn], h23[Bn];
#pragma unroll
            for (int b = 0; b < Bn; b++) {
                float4 h4 = ((const float4*)&hs[b][0])[j*32 + lane];
                h01[b] = pk2(h4.x, h4.y);
                h23[b] = pk2(h4.z, h4.w);
            }
#pragma unroll
            for (int b = 0; b < Bn; b++)
#pragma unroll
                for (int g = 0; g < 3; g++) {
                    fma2(acc2[g][b], wp[g][j][0], h01[b]);
                    fma2(acc2[g][b], wp[g][j][1], h23[b]);
                }
        }
        float acc[3][Bn];
#pragma unroll
        for (int g = 0; g < 3; g++)
#pragma unroll
            for (int b = 0; b < Bn; b++) {
                float2 p = upk2(acc2[g][b]);
                float v = p.x + p.y;
#pragma unroll
                for (int off = 16; off > 0; off >>= 1)
                    v += __shfl_xor_sync(0xffffffffu, v, off);
                acc[g][b] = v;
            }
        if (lane == 0) {
#pragma unroll
            for (int g = 0; g < 3; g++)
#pragma unroll
                for (int b = 0; b < Bn; b++) gbuf[w][g][b] = acc[g][b];
        }
        __syncthreads();

        if (is_comb) {
            int cc = tid % CHB;
            float hr = gbuf[cc][0][bcomb] + bhr;
            float hz = gbuf[cc][1][bcomb] + bhz;
            float hn = gbuf[cc][2][bcomb] + bhn;
            float r = 1.f / (1.f + expf(-(xr + hr)));
            float z = 1.f / (1.f + expf(-(xz + hz)));
            float n = tanhf(xn + r * hn);
            float hold = hs[bcomb][ccomb];
            float hnew = (1.f - z) * n + z * hold;
            g_hstate[bcomb*Cn + ccomb] = hnew;
            g_hrnn[((size_t)bcomb*Tn + t) * Cn + ccomb] = hnew;
            __threadfence();
        }
        __syncthreads();
        if (tid == 0) {
            atomicAdd(&g_bar, 1u);
            volatile unsigned* p = &g_bar;
            while (*p < target) __nanosleep(64);
        }
        target += NCTA_GRU;
        __syncthreads();
    }
}

// ---------------- gate MLP / energy -------------------------------------------
__global__ __launch_bounds__(128)
void energy_kernel(const float* __restrict__ gw1, const float* __restrict__ gb1,
                   const float* __restrict__ gw2, const float* __restrict__ gb2,
                   float* __restrict__ out_energy) {
    int tok = blockIdx.x;
    int tid = threadIdx.x, w = tid >> 5, lane = tid & 31;
    __shared__ float dots[32];
    const float* h = g_hrnn + (size_t)tok * Cn;
#pragma unroll
    for (int jj = 0; jj < 8; jj++) {
        int j = w * 8 + jj;
        const float* wr = gw1 + (size_t)j * Cn;
        float p = 0.f;
        for (int k = lane; k < Cn; k += 32) p += h[k] * wr[k];
#pragma unroll
        for (int off = 16; off > 0; off >>= 1) p += __shfl_xor_sync(0xffffffffu, p, off);
        if (lane == 0) dots[j] = p;
    }
    __syncthreads();
    if (tid == 0) {
        float a = gb2[0];
#pragma unroll
        for (int j = 0; j < 32; j++) a += tanhf(dots[j] + gb1[j]) * gw2[j];
        float e = 1.f / (1.f + expf(-a));
        g_energy[tok] = e;
        out_energy[tok] = e;
        if (e > 0.5f) atomicAdd(&g_active, 1);
    }
}

// ---------------- exact top-k via bitonic sort ---------------------------------
__global__ __launch_bounds__(1024)
void topk_kernel() {
    __shared__ unsigned long long keys[Tn];
    __shared__ int sel[KSEL];
    int b = blockIdx.x, tid = threadIdx.x;
    for (int e = tid; e < Tn; e += 1024) {
        unsigned u = __float_as_uint(g_energy[b*Tn + e]);
        u = (u & 0x80000000u) ? ~u : (u | 0x80000000u);
        keys[e] = ((unsigned long long)u << 32) | (unsigned)(Tn - 1 - e);
    }
    __syncthreads();
    for (int k = 2; k <= Tn; k <<= 1)
        for (int j = k >> 1; j > 0; j >>= 1) {
            int p = tid;
            int e = ((p & ~(j - 1)) << 1) | (p & (j - 1));
            int f = e | j;
            unsigned long long a = keys[e], c = keys[f];
            bool up = ((e & k) == 0);
            bool sw = up ? (a < c) : (a > c);
            if (sw) { keys[e] = c; keys[f] = a; }
            __syncthreads();
        }
    if (tid < KSEL) sel[tid] = Tn - 1 - (int)(keys[tid] & 0xffffffffull);
    __syncthreads();
    for (int k = 2; k <= KSEL; k <<= 1)
        for (int j = k >> 1; j > 0; j >>= 1) {
            if (tid < KSEL/2) {
                int p = tid;
                int e = ((p & ~(j - 1)) << 1) | (p & (j - 1));
                int f = e | j;
                int a = sel[e], c = sel[f];
                bool up = ((e & k) == 0);
                bool sw = up ? (a > c) : (a < c);
                if (sw) { sel[e] = c; sel[f] = a; }
            }
            __syncthreads();
        }
    if (tid < KSEL) g_idx[b*KSEL + tid] = sel[tid];
}

// ---------------- gather selected tokens (store tf32-rounded) ------------------
__global__ __launch_bounds__(192)
void gather_kernel() {
    int bk = blockIdx.x;
    int b = bk / KSEL;
    int t = g_idx[bk];
    if (threadIdx.x == 0) {
        g_gsel[bk] = g_energy[b*Tn + t];
        g_selmap[b*Tn + t] = bk % KSEL;
    }
    float4 v = ((const float4*)(g_hrnn + ((size_t)b*Tn + t) * Cn))[threadIdx.x];
    v.x = rna_tf32(v.x); v.y = rna_tf32(v.y);
    v.z = rna_tf32(v.z); v.w = rna_tf32(v.w);
    ((float4*)(g_xsel + (size_t)bk * Cn))[threadIdx.x] = v;
}

// ---------------- flash attention (stores tf32-rounded y) ----------------------
__global__ __launch_bounds__(256)
void attn_kernel() {
    extern __shared__ float sm[];
    float* Qs = sm;
    float* Ks = Qs + 64*65;
    float* Ps = Ks + 64*65;
    float* Vs = Ps + 64*65;
    int qt = blockIdx.x, bh = blockIdx.y;
    int b = bh / Hn, h = bh % Hn;
    int tid = threadIdx.x, tr = tid >> 4, tc = tid & 15;
    int q0 = qt * 64;
    const float* base = g_qkv + (size_t)b * KSEL * G3C;

    for (int i = tid; i < 1024; i += 256) {
        int r = i >> 4, d4 = i & 15;
        float4 v = __ldg((const float4*)(base + (size_t)(q0 + r)*G3C + h*64) + d4);
        Qs[r*65 + d4*4 + 0] = v.x; Qs[r*65 + d4*4 + 1] = v.y;
        Qs[r*65 + d4*4 + 2] = v.z; Qs[r*65 + d4*4 + 3] = v.w;
    }

    ull op[4][2];
    float m[4], l[4];
#pragma unroll
    for (int i = 0; i < 4; i++) {
        m[i] = -1e30f; l[i] = 0.f;
        op[i][0] = 0ull; op[i][1] = 0ull;
    }

    for (int kt = 0; kt <= qt; kt++) {
        int k0 = kt * 64;
        for (int i = tid; i < 1024; i += 256) {
            int c = i >> 4, d4 = i & 15;
            float4 kv = __ldg((const float4*)(base + (size_t)(k0 + c)*G3C + Cn + h*64) + d4);
            Ks[c*65 + d4*4 + 0] = kv.x; Ks[c*65 + d4*4 + 1] = kv.y;
            Ks[c*65 + d4*4 + 2] = kv.z; Ks[c*65 + d4*4 + 3] = kv.w;
            float4 vv = __ldg((const float4*)(base + (size_t)(k0 + c)*G3C + 2*Cn + h*64) + d4);
            ((float4*)(Vs + c*64))[d4] = vv;
        }
        __syncthreads();

        ull sp[4][2];
#pragma unroll
        for (int i = 0; i < 4; i++) { sp[i][0] = 0ull; sp[i][1] = 0ull; }
        for (int kk = 0; kk < 64; kk++) {
            ull ad[4], bp[2];
#pragma unroll
            for (int i = 0; i < 4; i++) ad[i] = dup2(Qs[(tr*4 + i)*65 + kk]);
            {
                float bb0 = Ks[(tc*4 + 0)*65 + kk];
                float bb1 = Ks[(tc*4 + 1)*65 + kk];
                float bb2 = Ks[(tc*4 + 2)*65 + kk];
                float bb3 = Ks[(tc*4 + 3)*65 + kk];
                bp[0] = pk2(bb0, bb1); bp[1] = pk2(bb2, bb3);
            }
#pragma unroll
            for (int i = 0; i < 4; i++) {
                fma2(sp[i][0], ad[i], bp[0]);
                fma2(sp[i][1], ad[i], bp[1]);
            }
        }
        float s[4][4];
#pragma unroll
        for (int i = 0; i < 4; i++) {
            float2 p0 = upk2(sp[i][0]), p1 = upk2(sp[i][1]);
            s[i][0] = p0.x * 0.125f; s[i][1] = p0.y * 0.125f;
            s[i][2] = p1.x * 0.125f; s[i][3] = p1.y * 0.125f;
        }
        if (kt == qt) {
#pragma unroll
            for (int i = 0; i < 4; i++)
#pragma unroll
                for (int j = 0; j < 4; j++)
                    if (k0 + tc*4 + j > q0 + tr*4 + i) s[i][j] = -1e30f;
        }
#pragma unroll
        for (int i = 0; i < 4; i++) {
            float rm = s[i][0];
#pragma unroll
            for (int j = 1; j < 4; j++) rm = fmaxf(rm, s[i][j]);
#pragma unroll
            for (int off = 8; off > 0; off >>= 1)
                rm = fmaxf(rm, __shfl_xor_sync(0xffffffffu, rm, off));
            float mn = fmaxf(m[i], rm);
            float alpha = expf(m[i] - mn);
            float rs = 0.f;
#pragma unroll
            for (int j = 0; j < 4; j++) {
                s[i][j] = expf(s[i][j] - mn);
                rs += s[i][j];
            }
#pragma unroll
            for (int off = 8; off > 0; off >>= 1)
                rs += __shfl_xor_sync(0xffffffffu, rs, off);
            l[i] = l[i] * alpha + rs;
            m[i] = mn;
            ull da = dup2(alpha);
            op[i][0] = mul2(op[i][0], da);
            op[i][1] = mul2(op[i][1], da);
#pragma unroll
            for (int j = 0; j < 4; j++) Ps[(tr*4 + i)*65 + tc*4 + j] = s[i][j];
        }
        __syncthreads();
        for (int c = 0; c < 64; c++) {
            ull pd[4], vp[2];
#pragma unroll
            for (int i = 0; i < 4; i++) pd[i] = dup2(Ps[(tr*4 + i)*65 + c]);
            {
                float4 vv = *(const float4*)(Vs + c*64 + tc*4);
                vp[0] = pk2(vv.x, vv.y); vp[1] = pk2(vv.z, vv.w);
            }
#pragma unroll
            for (int i = 0; i < 4; i++) {
                fma2(op[i][0], pd[i], vp[0]);
                fma2(op[i][1], pd[i], vp[1]);
            }
        }
        __syncthreads();
    }
#pragma unroll
    for (int i = 0; i < 4; i++) {
        float inv = 1.f / l[i];
        int row = b * KSEL + q0 + tr*4 + i;
        float2 p0 = upk2(op[i][0]), p1 = upk2(op[i][1]);
        float* dst = g_y + (size_t)row * Cn + h*64 + tc*4;
        dst[0] = rna_tf32(p0.x * inv); dst[1] = rna_tf32(p0.y * inv);
        dst[2] = rna_tf32(p1.x * inv); dst[3] = rna_tf32(p1.y * inv);
    }
}

// ---------------- LayerNorm (writes fp32 hln + tf32-rounded copy) --------------
__global__ __launch_bounds__(256)
void ln_kernel(const float* __restrict__ g, const float* __restrict__ bb,
               float* __restrict__ hlnr) {
    __shared__ float xrow[Cn];
    __shared__ float rbuf[16];
    int tok = blockIdx.x, tid = threadIdx.x;
    int b = tok >> 11;
    int sel = g_selmap[tok];
    float s = 0.f, s2 = 0.f;
    for (int c = tid; c < Cn; c += 256) {
        float v = g_hrnn[(size_t)tok*Cn + c];
        if (sel >= 0) v += g_weighted[((size_t)(b*KSEL + sel))*Cn + c];
        xrow[c] = v; s += v; s2 += v*v;
    }
#pragma unroll
    for (int off = 16; off > 0; off >>= 1) {
        s  += __shfl_xor_sync(0xffffffffu, s, off);
        s2 += __shfl_xor_sync(0xffffffffu, s2, off);
    }
    int w = tid >> 5;
    if ((tid & 31) == 0) { rbuf[w] = s; rbuf[8 + w] = s2; }
    __syncthreads();
    if (tid == 0) {
        float S = 0.f, S2 = 0.f;
        for (int i = 0; i < 8; i++) { S += rbuf[i]; S2 += rbuf[8 + i]; }
        float mu = S / (float)Cn;
        float var = S2 / (float)Cn - mu*mu;
        rbuf[0] = mu; rbuf[1] = rsqrtf(var + 1e-5f);
    }
    __syncthreads();
    float mu = rbuf[0], inv = rbuf[1];
    for (int c = tid; c < Cn; c += 256) {
        float v = (xrow[c] - mu) * inv * g[c] + bb[c];
        g_hln[(size_t)tok*Cn + c] = v;
        hlnr[(size_t)tok*Cn + c] = rna_tf32(v);
    }
}

// ---------------- finalize ------------------------------------------------------
__global__ void finalize_kernel(float* out) {
    out[(size_t)BT*Cn + BT] = (float)g_active;
}

// ---------------- launcher ------------------------------------------------------
extern "C" void kernel_launch(void* const* d_in, const int* in_sizes, int n_in,
                              void* d_out, int out_size) {
    const float* x      = (const float*)d_in[0];
    const float* W_ih   = (const float*)d_in[1];
    const float* W_hh   = (const float*)d_in[2];
    const float* b_ih   = (const float*)d_in[3];
    const float* b_hh   = (const float*)d_in[4];
    const float* gate_w1= (const float*)d_in[5];
    const float* gate_b1= (const float*)d_in[6];
    const float* gate_w2= (const float*)d_in[7];
    const float* gate_b2= (const float*)d_in[8];
    const float* qkv_w  = (const float*)d_in[9];
    const float* qkv_b  = (const float*)d_in[10];
    const float* proj_w = (const float*)d_in[11];
    const float* proj_b = (const float*)d_in[12];
    const float* ln_g   = (const float*)d_in[13];
    const float* ln_b   = (const float*)d_in[14];
    const float* ffn_w1 = (const float*)d_in[15];
    const float* ffn_b1 = (const float*)d_in[16];
    const float* ffn_w2 = (const float*)d_in[17];
    const float* ffn_b2 = (const float*)d_in[18];
    float* out = (float*)d_out;

    float *p_xi, *p_xsel, *p_qkv, *p_y, *p_weighted, *p_hln, *p_mid, *p_wscr;
    cudaGetSymbolAddress((void**)&p_xi,       g_xi);
    cudaGetSymbolAddress((void**)&p_xsel,     g_xsel);
    cudaGetSymbolAddress((void**)&p_qkv,      g_qkv);
    cudaGetSymbolAddress((void**)&p_y,        g_y);
    cudaGetSymbolAddress((void**)&p_weighted, g_weighted);
    cudaGetSymbolAddress((void**)&p_hln,      g_hln);
    cudaGetSymbolAddress((void**)&p_mid,      g_mid);
    cudaGetSymbolAddress((void**)&p_wscr,     g_wscr);
    float* p_gsel; cudaGetSymbolAddress((void**)&p_gsel, g_gsel);
    float* p_energy_out = out + (size_t)BT*Cn;
    float* p_hlnr = p_xi;   // reuse xi scratch (free after GRU)

    const int ATTN_SMEM = (3*64*65 + 64*64) * 4;
    cudaFuncSetAttribute(attn_kernel, cudaFuncAttributeMaxDynamicSharedMemorySize, ATTN_SMEM);
    cudaFuncSetAttribute(gemm_tc_kernel<0>, cudaFuncAttributeMaxDynamicSharedMemorySize, GSM_BYTES);
    cudaFuncSetAttribute(gemm_tc_kernel<1>, cudaFuncAttributeMaxDynamicSharedMemorySize, GSM_BYTES);
    cudaFuncSetAttribute(gemm_tc_kernel<2>, cudaFuncAttributeMaxDynamicSharedMemorySize, GSM_BYTES);
    cudaFuncSetAttribute(gemm_tc_kernel<3>, cudaFuncAttributeMaxDynamicSharedMemorySize, GSM_BYTES);

    // 0) init
    init_kernel<<<64, 256>>>();

    // 1) round weights to tf32 (rna) into scratch
    cvtw_kernel<<<(WTOTAL + 255)/256, 256>>>(qkv_w, proj_w, ffn_w1, ffn_w2);

    // 2) xi = x @ W_ih^T + b_ih  (fp32 FFMA2)
    gemm_kernel<<<dim3(G3C/128, BT/128), 256>>>(x, W_ih, b_ih, p_xi, BT, G3C, Cn);

    // 3) GRU scan
    gru_kernel<<<NCTA_GRU, 192>>>(p_xi, W_hh, b_hh);

    // 4) energy
    energy_kernel<<<BT, 128>>>(gate_w1, gate_b1, gate_w2, gate_b2, p_energy_out);

    // 5) top-k
    topk_kernel<<<Bn, 1024>>>();

    // 6) gather (rounds xsel)
    gather_kernel<<<BKn, 192>>>();

    // 7) qkv GEMM
    gemm_tc_kernel<0><<<dim3(G3C/128, BKn/128), 256, GSM_BYTES>>>(
        p_xsel, p_wscr + WOFF_QKV, qkv_b, nullptr, p_qkv, BKn, G3C, Cn);

    // 8) attention (rounds y)
    attn_kernel<<<dim3(KSEL/64, Bn*Hn), 256, ATTN_SMEM>>>();

    // 9) proj GEMM (row-scale)
    gemm_tc_kernel<2><<<dim3(Cn/128, BKn/128), 256, GSM_BYTES>>>(
        p_y, p_wscr + WOFF_PROJ, proj_b, p_gsel, p_weighted, BKn, Cn, Cn);

    // 10) LayerNorm (writes fp32 + rounded copies)
    ln_kernel<<<BT, 256>>>(ln_g, ln_b, p_hlnr);

    // 11) ffn1 GEMM (gelu, rounded output)
    gemm_tc_kernel<1><<<dim3(DFF/128, BT/128), 256, GSM_BYTES>>>(
        p_hlnr, p_wscr + WOFF_FFN1, ffn_b1, nullptr, p_mid, BT, DFF, Cn);

    // 12) ffn2 GEMM (residual) -> out
    gemm_tc_kernel<3><<<dim3(Cn/128, BT/128), 256, GSM_BYTES>>>(
        p_mid, p_wscr + WOFF_FFN2, ffn_b2, p_hln, out, BT, Cn, DFF);

    // 13) active count
    finalize_kernel<<<1, 1>>>(out);

    (void)in_sizes; (void)n_in; (void)out_size;
}

// round 7
// speedup vs baseline: 1.1014x; 1.0107x over previous
#include <cuda_runtime.h>
#include <math.h>
#include <stdint.h>

#define Bn 8
#define Tn 2048
#define Cn 768
#define Hn 12
#define KSEL 1024
#define DFF 3072
#define BT (Bn*Tn)      /* 16384 */
#define BKn (Bn*KSEL)   /* 8192 */
#define G3C (3*Cn)      /* 2304 */

typedef unsigned long long ull;

// ---------------- f32x2 packed helpers --------------------------------------
__device__ __forceinline__ ull pk2(float x, float y) {
    ull r; asm("mov.b64 %0, {%1, %2};" : "=l"(r) : "f"(x), "f"(y)); return r;
}
__device__ __forceinline__ ull dup2(float x) { return pk2(x, x); }
__device__ __forceinline__ void fma2(ull &acc, ull a, ull b) {
    asm("fma.rn.f32x2 %0, %1, %2, %0;" : "+l"(acc) : "l"(a), "l"(b));
}
__device__ __forceinline__ ull mul2(ull a, ull b) {
    ull r; asm("mul.rn.f32x2 %0, %1, %2;" : "=l"(r) : "l"(a), "l"(b)); return r;
}
__device__ __forceinline__ float2 upk2(ull v) {
    float2 r; asm("mov.b64 {%0, %1}, %2;" : "=f"(r.x), "=f"(r.y) : "l"(v)); return r;
}
__device__ __forceinline__ float rna_tf32(float x) {
    unsigned u; asm("cvt.rna.tf32.f32 %0, %1;" : "=r"(u) : "f"(x));
    return __uint_as_float(u);
}

// ---------------- cp.async helpers ------------------------------------------
__device__ __forceinline__ uint32_t smem_u32(const void* p) {
    uint32_t a; asm("{ .reg .u64 t; cvta.to.shared.u64 t, %1; cvt.u32.u64 %0, t; }"
                    : "=r"(a) : "l"(p));
    return a;
}
__device__ __forceinline__ void cp16(uint32_t saddr, const void* gaddr) {
    asm volatile("cp.async.cg.shared.global [%0], [%1], 16;"
                 :: "r"(saddr), "l"(__cvta_generic_to_global(gaddr)));
}
__device__ __forceinline__ void cp_commit() { asm volatile("cp.async.commit_group;"); }
template<int N>
__device__ __forceinline__ void cp_waitg() {
    asm volatile("cp.async.wait_group %0;" :: "n"(N) : "memory");
}

// ---------------- scratch -----------------------------------------------------
__device__ float g_xi[(size_t)BT*G3C];     // xi; later reused for rounded hln
__device__ float g_hrnn[(size_t)BT*Cn];
__device__ float g_hstate[Bn*Cn];
__device__ float g_energy[BT];
__device__ int   g_idx[BKn];
__device__ int   g_selmap[BT];
__device__ float g_xsel[(size_t)BKn*Cn];
__device__ float g_gsel[BKn];
__device__ float g_qkv[(size_t)BKn*G3C];
__device__ float g_y[(size_t)BKn*Cn];
__device__ float g_weighted[(size_t)BKn*Cn];
__device__ float g_hln[(size_t)BT*Cn];
__device__ float g_mid[(size_t)BT*DFF];
__device__ float g_wscr[7077888];          // rounded weights: qkv|proj|ffn1|ffn2
__device__ unsigned g_bar;
__device__ int g_active;

#define WOFF_QKV  0
#define WOFF_PROJ 1769472
#define WOFF_FFN1 2359296
#define WOFF_FFN2 4718592
#define WTOTAL    7077888

// ---------------- init --------------------------------------------------------
__global__ void init_kernel() {
    int tid = blockIdx.x * blockDim.x + threadIdx.x;
    if (tid == 0) { g_bar = 0u; g_active = 0; }
    for (int i = tid; i < Bn*Cn; i += gridDim.x*blockDim.x) g_hstate[i] = 0.f;
    for (int i = tid; i < BT;    i += gridDim.x*blockDim.x) g_selmap[i] = -1;
}

// ---------------- weight rounding (rna -> tf32 bit pattern) -------------------
__global__ __launch_bounds__(256)
void cvtw_kernel(const float* __restrict__ qkvw, const float* __restrict__ projw,
                 const float* __restrict__ w1, const float* __restrict__ w2) {
    int i = blockIdx.x * 256 + threadIdx.x;
    if (i >= WTOTAL) return;
    float v;
    if (i < WOFF_PROJ)       v = qkvw[i - WOFF_QKV];
    else if (i < WOFF_FFN1)  v = projw[i - WOFF_PROJ];
    else if (i < WOFF_FFN2)  v = w1[i - WOFF_FFN1];
    else                     v = w2[i - WOFF_FFN2];
    g_wscr[i] = rna_tf32(v);
}

// ============================================================================
// TF32 tensor-core GEMM (mma.sync, cp.async-fed, 3-stage, 2 CTAs/SM):
// C[M,N] = A[M,K]@W[N,K]^T + bias. Inputs pre-rounded to tf32.
// 128x128 CTA tile, k-tile 32, XOR-swizzled SMEM.
// EP: 0 none, 1 gelu(exact erf, store rounded), 2 row-scale, 3 residual
// ============================================================================
#define GSM_BYTES 98304   /* 3 stages x (A 16KB + W 16KB) */

template<int EP>
__global__ __launch_bounds__(256, 2)
void gemm_tc_kernel(const float* __restrict__ A, const float* __restrict__ W,
                    const float* __restrict__ bias, const float* __restrict__ extra,
                    float* __restrict__ Cc, int M, int N, int K) {
    extern __shared__ float smdyn[];
    uint32_t sbase = smem_u32(smdyn);
    int tid = threadIdx.x;
    int m0 = blockIdx.y * 128, n0 = blockIdx.x * 128;
    int wid = tid >> 5, L = tid & 31;
    int warp_m = wid >> 2;        // 0..1 (64 rows)
    int warp_n = wid & 3;         // 0..3 (32 cols)
    int r = L >> 2, c4 = L & 3;

    float cacc[4][4][4];
#pragma unroll
    for (int mt = 0; mt < 4; mt++)
#pragma unroll
        for (int nt = 0; nt < 4; nt++)
#pragma unroll
            for (int q = 0; q < 4; q++) cacc[mt][nt][q] = 0.f;

    // stage layout (floats): [st*8192 + 0 : A 4096][st*8192 + 4096 : W 4096]
    // swizzled: elem(row,k) at row*32 + (((k>>2) ^ (row&7))<<2) + (k&3)
    auto load_tile = [&](int c, int st) {
        const float* Ag = A + (size_t)m0 * K + c * 32;
        const float* Wg = W + (size_t)n0 * K + c * 32;
        uint32_t ab = sbase + st * 32768;
        uint32_t wb = ab + 16384;
#pragma unroll
        for (int i = 0; i < 4; i++) {
            int idx = tid + 256 * i;          // 0..1023
            int row = idx >> 3, g = idx & 7;
            uint32_t so = row * 128 + ((g ^ (row & 7)) << 4);
            cp16(ab + so, Ag + (size_t)row * K + g * 4);
            cp16(wb + so, Wg + (size_t)row * K + g * 4);
        }
        cp_commit();
    };

    const int NC = K >> 5;
    load_tile(0, 0);
    if (NC > 1) load_tile(1, 1);

    int st = 0, st2 = (NC > 2) ? 2 : 0;   // st2 = stage for c+2
    for (int c = 0; c < NC; c++) {
        if (c + 2 < NC) {
            load_tile(c + 2, st2);
            st2 = (st2 == 2) ? 0 : st2 + 1;
            cp_waitg<2>();
        } else if (c + 1 < NC) {
            cp_waitg<1>();
        } else {
            cp_waitg<0>();
        }
        __syncthreads();

        const float* As = smdyn + st * 8192;
        const float* Ws = As + 4096;
        st = (st == 2) ? 0 : st + 1;
#pragma unroll
        for (int s = 0; s < 4; s++) {
            int g0 = 2 * s, g1 = 2 * s + 1;
            unsigned a[4][4];
#pragma unroll
            for (int mt = 0; mt < 4; mt++) {
                int r0 = warp_m * 64 + mt * 16 + r, r1 = r0 + 8;
                a[mt][0] = __float_as_uint(As[r0*32 + ((g0 ^ r) << 2) + c4]);
                a[mt][1] = __float_as_uint(As[r1*32 + ((g0 ^ r) << 2) + c4]);
                a[mt][2] = __float_as_uint(As[r0*32 + ((g1 ^ r) << 2) + c4]);
                a[mt][3] = __float_as_uint(As[r1*32 + ((g1 ^ r) << 2) + c4]);
            }
            unsigned bq[4][2];
#pragma unroll
            for (int nt = 0; nt < 4; nt++) {
                int nn = warp_n * 32 + nt * 8 + r;
                bq[nt][0] = __float_as_uint(Ws[nn*32 + ((g0 ^ r) << 2) + c4]);
                bq[nt][1] = __float_as_uint(Ws[nn*32 + ((g1 ^ r) << 2) + c4]);
            }
#pragma unroll
            for (int mt = 0; mt < 4; mt++)
#pragma unroll
                for (int nt = 0; nt < 4; nt++) {
                    asm volatile(
                        "mma.sync.aligned.m16n8k8.row.col.f32.tf32.tf32.f32 "
                        "{%0,%1,%2,%3}, {%4,%5,%6,%7}, {%8,%9}, {%0,%1,%2,%3};"
                        : "+f"(cacc[mt][nt][0]), "+f"(cacc[mt][nt][1]),
                          "+f"(cacc[mt][nt][2]), "+f"(cacc[mt][nt][3])
                        : "r"(a[mt][0]), "r"(a[mt][1]), "r"(a[mt][2]), "r"(a[mt][3]),
                          "r"(bq[nt][0]), "r"(bq[nt][1]));
                }
        }
        __syncthreads();
    }

    // ---- epilogue ----
#pragma unroll
    for (int mt = 0; mt < 4; mt++) {
        int gm = m0 + warp_m*64 + mt*16 + r;
        float rs0 = (EP == 2) ? extra[gm] : 0.f;
        float rs1 = (EP == 2) ? extra[gm + 8] : 0.f;
#pragma unroll
        for (int nt = 0; nt < 4; nt++) {
            int gn = n0 + warp_n*32 + nt*8 + 2*c4;
            float b0 = bias[gn], b1 = bias[gn + 1];
#pragma unroll
            for (int half = 0; half < 2; half++) {
                int row = gm + half*8;
                float v0 = cacc[mt][nt][half*2 + 0] + b0;
                float v1 = cacc[mt][nt][half*2 + 1] + b1;
                if (EP == 1) {
                    v0 = 0.5f * v0 * (1.f + erff(v0 * 0.70710678118654752f));
                    v1 = 0.5f * v1 * (1.f + erff(v1 * 0.70710678118654752f));
                    v0 = rna_tf32(v0);
                    v1 = rna_tf32(v1);
                }
                if (EP == 2) { float rs = half ? rs1 : rs0; v0 *= rs; v1 *= rs; }
                if (EP == 3) {
                    v0 += extra[(size_t)row * N + gn];
                    v1 += extra[(size_t)row * N + gn + 1];
                }
                *(float2*)(Cc + (size_t)row * N + gn) = make_float2(v0, v1);
            }
        }
    }
}

// ---------------- fp32 SGEMM (FFMA2) — xi only (pre-selection) ----------------
__global__ __launch_bounds__(256, 2)
void gemm_kernel(const float* __restrict__ A, const float* __restrict__ W,
                 const float* __restrict__ bias,
                 float* __restrict__ Cc, int M, int N, int K) {
    __shared__ float As[2][8][128];
    __shared__ float Bs[2][8][128];
    int tid = threadIdx.x;
    int m0 = blockIdx.y * 128, n0 = blockIdx.x * 128;
    int tr = tid >> 4, tc = tid & 15;

    ull acc[8][4];
#pragma unroll
    for (int i = 0; i < 8; i++)
#pragma unroll
        for (int j = 0; j < 4; j++) acc[i][j] = 0ull;

    int lr = tid >> 1;
    int lc = (tid & 1) * 4;
    const float* Ap = A + (size_t)(m0 + lr) * K + lc;
    const float* Wp = W + (size_t)(n0 + lr) * K + lc;

    {
        float4 av = *(const float4*)(Ap);
        float4 wv = *(const float4*)(Wp);
        As[0][lc + 0][lr] = av.x; As[0][lc + 1][lr] = av.y;
        As[0][lc + 2][lr] = av.z; As[0][lc + 3][lr] = av.w;
        Bs[0][lc + 0][lr] = wv.x; Bs[0][lc + 1][lr] = wv.y;
        Bs[0][lc + 2][lr] = wv.z; Bs[0][lc + 3][lr] = wv.w;
    }
    __syncthreads();

    int buf = 0;
    for (int kt = 8; kt <= K; kt += 8) {
        float4 av, wv;
        bool more = (kt < K);
        if (more) {
            av = *(const float4*)(Ap + kt);
            wv = *(const float4*)(Wp + kt);
        }
#pragma unroll
        for (int kk = 0; kk < 8; kk++) {
            float4 a0 = *(const float4*)&As[buf][kk][tr*8];
            float4 a1 = *(const float4*)&As[buf][kk][tr*8 + 4];
            float4 b0 = *(const float4*)&Bs[buf][kk][tc*8];
            float4 b1 = *(const float4*)&Bs[buf][kk][tc*8 + 4];
            ull bp[4] = { pk2(b0.x,b0.y), pk2(b0.z,b0.w),
                          pk2(b1.x,b1.y), pk2(b1.z,b1.w) };
            ull ad[8] = { dup2(a0.x), dup2(a0.y), dup2(a0.z), dup2(a0.w),
                          dup2(a1.x), dup2(a1.y), dup2(a1.z), dup2(a1.w) };
#pragma unroll
            for (int i = 0; i < 8; i++)
#pragma unroll
                for (int jp = 0; jp < 4; jp++) fma2(acc[i][jp], ad[i], bp[jp]);
        }
        if (more) {
            int nb = buf ^ 1;
            As[nb][lc + 0][lr] = av.x; As[nb][lc + 1][lr] = av.y;
            As[nb][lc + 2][lr] = av.z; As[nb][lc + 3][lr] = av.w;
            Bs[nb][lc + 0][lr] = wv.x; Bs[nb][lc + 1][lr] = wv.y;
            Bs[nb][lc + 2][lr] = wv.z; Bs[nb][lc + 3][lr] = wv.w;
        }
        __syncthreads();
        buf ^= 1;
    }

#pragma unroll
    for (int i = 0; i < 8; i++) {
        int m = m0 + tr*8 + i;
#pragma unroll
        for (int jp = 0; jp < 4; jp++) {
            float2 p = upk2(acc[i][jp]);
            float vals[2] = { p.x, p.y };
#pragma unroll
            for (int h = 0; h < 2; h++) {
                int n = n0 + tc*8 + jp*2 + h;
                Cc[(size_t)m * N + n] = vals[h] + bias[n];
            }
        }
    }
}

// ---------------- GRU persistent kernel ---------------------------------------
#define NCTA_GRU 128
#define CHB 6
__global__ __launch_bounds__(192, 1)
void gru_kernel(const float* __restrict__ xi, const float* __restrict__ Whh,
                const float* __restrict__ bhh) {
    __shared__ float hs[Bn][Cn];
    __shared__ float gbuf[CHB][3][Bn];
    int tid = threadIdx.x, w = tid >> 5, lane = tid & 31;
    int c0 = blockIdx.x * CHB;
    int ch = c0 + w;

    ull wp[3][6][2];
#pragma unroll
    for (int g = 0; g < 3; g++)
#pragma unroll
        for (int j = 0; j < 6; j++) {
            float4 v = __ldg((const float4*)(Whh + (size_t)(g*Cn + ch) * Cn) + (j*32 + lane));
            wp[g][j][0] = pk2(v.x, v.y);
            wp[g][j][1] = pk2(v.z, v.w);
        }

    bool is_comb = tid < (Bn * CHB);
    int bcomb = 0, ccomb = 0;
    float bhr = 0.f, bhz = 0.f, bhn = 0.f;
    if (is_comb) {
        bcomb = tid / CHB; ccomb = c0 + tid % CHB;
        bhr = __ldg(bhh + ccomb);
        bhz = __ldg(bhh + Cn + ccomb);
        bhn = __ldg(bhh + 2*Cn + ccomb);
    }

    unsigned target = NCTA_GRU;
    for (int t = 0; t < Tn; t++) {
        const float4* hp = (const float4*)g_hstate;
        float4* hd = (float4*)&hs[0][0];
#pragma unroll
        for (int i = 0; i < 8; i++) hd[tid + i*192] = __ldcg(hp + tid + i*192);

        float xr = 0.f, xz = 0.f, xn = 0.f;
        if (is_comb) {
            const float* xrow = xi + ((size_t)bcomb*Tn + t) * G3C + ccomb;
            xr = __ldg(xrow); xz = __ldg(xrow + Cn); xn = __ldg(xrow + 2*Cn);
        }
        __syncthreads();

        ull acc2[3][Bn];
#pragma unroll
        for (int g = 0; g < 3; g++)
#pragma unroll
            for (int b = 0; b < Bn; b++) acc2[g][b] = 0ull;

#pragma unroll
        for (int j = 0; j < 6; j++) {
            ull h01[Bn], h23[Bn];
#pragma unroll
            for (int b = 0; b < Bn; b++) {
                float4 h4 = ((const float4*)&hs[b][0])[j*32 + lane];
                h01[b] = pk2(h4.x, h4.y);
                h23[b] = pk2(h4.z, h4.w);
            }
#pragma unroll
            for (int b = 0; b < Bn; b++)
#pragma unroll
                for (int g = 0; g < 3; g++) {
                    fma2(acc2[g][b], wp[g][j][0], h01[b]);
                    fma2(acc2[g][b], wp[g][j][1], h23[b]);
                }
        }
        float acc[3][Bn];
#pragma unroll
        for (int g = 0; g < 3; g++)
#pragma unroll
            for (int b = 0; b < Bn; b++) {
                float2 p = upk2(acc2[g][b]);
                float v = p.x + p.y;
#pragma unroll
                for (int off = 16; off > 0; off >>= 1)
                    v += __shfl_xor_sync(0xffffffffu, v, off);
                acc[g][b] = v;
            }
        if (lane == 0) {
#pragma unroll
            for (int g = 0; g < 3; g++)
#pragma unroll
                for (int b = 0; b < Bn; b++) gbuf[w][g][b] = acc[g][b];
        }
        __syncthreads();

        if (is_comb) {
            int cc = tid % CHB;
            float hr = gbuf[cc][0][bcomb] + bhr;
            float hz = gbuf[cc][1][bcomb] + bhz;
            float hn = gbuf[cc][2][bcomb] + bhn;
            float r = 1.f / (1.f + expf(-(xr + hr)));
            float z = 1.f / (1.f + expf(-(xz + hz)));
            float n = tanhf(xn + r * hn);
            float hold = hs[bcomb][ccomb];
            float hnew = (1.f - z) * n + z * hold;
            g_hstate[bcomb*Cn + ccomb] = hnew;
            g_hrnn[((size_t)bcomb*Tn + t) * Cn + ccomb] = hnew;
            __threadfence();
        }
        __syncthreads();
        if (tid == 0) {
            atomicAdd(&g_bar, 1u);
            volatile unsigned* p = &g_bar;
            while (*p < target) __nanosleep(64);
        }
        target += NCTA_GRU;
        __syncthreads();
    }
}

// ---------------- gate MLP / energy -------------------------------------------
__global__ __launch_bounds__(128)
void energy_kernel(const float* __restrict__ gw1, const float* __restrict__ gb1,
                   const float* __restrict__ gw2, const float* __restrict__ gb2,
                   float* __restrict__ out_energy) {
    int tok = blockIdx.x;
    int tid = threadIdx.x, w = tid >> 5, lane = tid & 31;
    __shared__ float dots[32];
    const float* h = g_hrnn + (size_t)tok * Cn;
#pragma unroll
    for (int jj = 0; jj < 8; jj++) {
        int j = w * 8 + jj;
        const float* wr = gw1 + (size_t)j * Cn;
        float p = 0.f;
        for (int k = lane; k < Cn; k += 32) p += h[k] * wr[k];
#pragma unroll
        for (int off = 16; off > 0; off >>= 1) p += __shfl_xor_sync(0xffffffffu, p, off);
        if (lane == 0) dots[j] = p;
    }
    __syncthreads();
    if (tid == 0) {
        float a = gb2[0];
#pragma unroll
        for (int j = 0; j < 32; j++) a += tanhf(dots[j] + gb1[j]) * gw2[j];
        float e = 1.f / (1.f + expf(-a));
        g_energy[tok] = e;
        out_energy[tok] = e;
        if (e > 0.5f) atomicAdd(&g_active, 1);
    }
}

// ---------------- exact top-k via bitonic sort ---------------------------------
__global__ __launch_bounds__(1024)
void topk_kernel() {
    __shared__ unsigned long long keys[Tn];
    __shared__ int sel[KSEL];
    int b = blockIdx.x, tid = threadIdx.x;
    for (int e = tid; e < Tn; e += 1024) {
        unsigned u = __float_as_uint(g_energy[b*Tn + e]);
        u = (u & 0x80000000u) ? ~u : (u | 0x80000000u);
        keys[e] = ((unsigned long long)u << 32) | (unsigned)(Tn - 1 - e);
    }
    __syncthreads();
    for (int k = 2; k <= Tn; k <<= 1)
        for (int j = k >> 1; j > 0; j >>= 1) {
            int p = tid;
            int e = ((p & ~(j - 1)) << 1) | (p & (j - 1));
            int f = e | j;
            unsigned long long a = keys[e], c = keys[f];
            bool up = ((e & k) == 0);
            bool sw = up ? (a < c) : (a > c);
            if (sw) { keys[e] = c; keys[f] = a; }
            __syncthreads();
        }
    if (tid < KSEL) sel[tid] = Tn - 1 - (int)(keys[tid] & 0xffffffffull);
    __syncthreads();
    for (int k = 2; k <= KSEL; k <<= 1)
        for (int j = k >> 1; j > 0; j >>= 1) {
            if (tid < KSEL/2) {
                int p = tid;
                int e = ((p & ~(j - 1)) << 1) | (p & (j - 1));
                int f = e | j;
                int a = sel[e], c = sel[f];
                bool up = ((e & k) == 0);
                bool sw = up ? (a > c) : (a < c);
                if (sw) { sel[e] = c; sel[f] = a; }
            }
            __syncthreads();
        }
    if (tid < KSEL) g_idx[b*KSEL + tid] = sel[tid];
}

// ---------------- gather selected tokens (store tf32-rounded) ------------------
__global__ __launch_bounds__(192)
void gather_kernel() {
    int bk = blockIdx.x;
    int b = bk / KSEL;
    int t = g_idx[bk];
    if (threadIdx.x == 0) {
        g_gsel[bk] = g_energy[b*Tn + t];
        g_selmap[b*Tn + t] = bk % KSEL;
    }
    float4 v = ((const float4*)(g_hrnn + ((size_t)b*Tn + t) * Cn))[threadIdx.x];
    v.x = rna_tf32(v.x); v.y = rna_tf32(v.y);
    v.z = rna_tf32(v.z); v.w = rna_tf32(v.w);
    ((float4*)(g_xsel + (size_t)bk * Cn))[threadIdx.x] = v;
}

// ---------------- flash attention (stores tf32-rounded y) ----------------------
__global__ __launch_bounds__(256)
void attn_kernel() {
    extern __shared__ float sm[];
    float* Qs = sm;
    float* Ks = Qs + 64*65;
    float* Ps = Ks + 64*65;
    float* Vs = Ps + 64*65;
    int qt = blockIdx.x, bh = blockIdx.y;
    int b = bh / Hn, h = bh % Hn;
    int tid = threadIdx.x, tr = tid >> 4, tc = tid & 15;
    int q0 = qt * 64;
    const float* base = g_qkv + (size_t)b * KSEL * G3C;

    for (int i = tid; i < 1024; i += 256) {
        int r = i >> 4, d4 = i & 15;
        float4 v = __ldg((const float4*)(base + (size_t)(q0 + r)*G3C + h*64) + d4);
        Qs[r*65 + d4*4 + 0] = v.x; Qs[r*65 + d4*4 + 1] = v.y;
        Qs[r*65 + d4*4 + 2] = v.z; Qs[r*65 + d4*4 + 3] = v.w;
    }

    ull op[4][2];
    float m[4], l[4];
#pragma unroll
    for (int i = 0; i < 4; i++) {
        m[i] = -1e30f; l[i] = 0.f;
        op[i][0] = 0ull; op[i][1] = 0ull;
    }

    for (int kt = 0; kt <= qt; kt++) {
        int k0 = kt * 64;
        for (int i = tid; i < 1024; i += 256) {
            int c = i >> 4, d4 = i & 15;
            float4 kv = __ldg((const float4*)(base + (size_t)(k0 + c)*G3C + Cn + h*64) + d4);
            Ks[c*65 + d4*4 + 0] = kv.x; Ks[c*65 + d4*4 + 1] = kv.y;
            Ks[c*65 + d4*4 + 2] = kv.z; Ks[c*65 + d4*4 + 3] = kv.w;
            float4 vv = __ldg((const float4*)(base + (size_t)(k0 + c)*G3C + 2*Cn + h*64) + d4);
            ((float4*)(Vs + c*64))[d4] = vv;
        }
        __syncthreads();

        ull sp[4][2];
#pragma unroll
        for (int i = 0; i < 4; i++) { sp[i][0] = 0ull; sp[i][1] = 0ull; }
        for (int kk = 0; kk < 64; kk++) {
            ull ad[4], bp[2];
#pragma unroll
            for (int i = 0; i < 4; i++) ad[i] = dup2(Qs[(tr*4 + i)*65 + kk]);
            {
                float bb0 = Ks[(tc*4 + 0)*65 + kk];
                float bb1 = Ks[(tc*4 + 1)*65 + kk];
                float bb2 = Ks[(tc*4 + 2)*65 + kk];
                float bb3 = Ks[(tc*4 + 3)*65 + kk];
                bp[0] = pk2(bb0, bb1); bp[1] = pk2(bb2, bb3);
            }
#pragma unroll
            for (int i = 0; i < 4; i++) {
                fma2(sp[i][0], ad[i], bp[0]);
                fma2(sp[i][1], ad[i], bp[1]);
            }
        }
        float s[4][4];
#pragma unroll
        for (int i = 0; i < 4; i++) {
            float2 p0 = upk2(sp[i][0]), p1 = upk2(sp[i][1]);
            s[i][0] = p0.x * 0.125f; s[i][1] = p0.y * 0.125f;
            s[i][2] = p1.x * 0.125f; s[i][3] = p1.y * 0.125f;
        }
        if (kt == qt) {
#pragma unroll
            for (int i = 0; i < 4; i++)
#pragma unroll
                for (int j = 0; j < 4; j++)
                    if (k0 + tc*4 + j > q0 + tr*4 + i) s[i][j] = -1e30f;
        }
#pragma unroll
        for (int i = 0; i < 4; i++) {
            float rm = s[i][0];
#pragma unroll
            for (int j = 1; j < 4; j++) rm = fmaxf(rm, s[i][j]);
#pragma unroll
            for (int off = 8; off > 0; off >>= 1)
                rm = fmaxf(rm, __shfl_xor_sync(0xffffffffu, rm, off));
            float mn = fmaxf(m[i], rm);
            float alpha = expf(m[i] - mn);
            float rs = 0.f;
#pragma unroll
            for (int j = 0; j < 4; j++) {
                s[i][j] = expf(s[i][j] - mn);
                rs += s[i][j];
            }
#pragma unroll
            for (int off = 8; off > 0; off >>= 1)
                rs += __shfl_xor_sync(0xffffffffu, rs, off);
            l[i] = l[i] * alpha + rs;
            m[i] = mn;
            ull da = dup2(alpha);
            op[i][0] = mul2(op[i][0], da);
            op[i][1] = mul2(op[i][1], da);
#pragma unroll
            for (int j = 0; j < 4; j++) Ps[(tr*4 + i)*65 + tc*4 + j] = s[i][j];
        }
        __syncthreads();
        for (int c = 0; c < 64; c++) {
            ull pd[4], vp[2];
#pragma unroll
            for (int i = 0; i < 4; i++) pd[i] = dup2(Ps[(tr*4 + i)*65 + c]);
            {
                float4 vv = *(const float4*)(Vs + c*64 + tc*4);
                vp[0] = pk2(vv.x, vv.y); vp[1] = pk2(vv.z, vv.w);
            }
#pragma unroll
            for (int i = 0; i < 4; i++) {
                fma2(op[i][0], pd[i], vp[0]);
                fma2(op[i][1], pd[i], vp[1]);
            }
        }
        __syncthreads();
    }
#pragma unroll
    for (int i = 0; i < 4; i++) {
        float inv = 1.f / l[i];
        int row = b * KSEL + q0 + tr*4 + i;
        float2 p0 = upk2(op[i][0]), p1 = upk2(op[i][1]);
        float* dst = g_y + (size_t)row * Cn + h*64 + tc*4;
        dst[0] = rna_tf32(p0.x * inv); dst[1] = rna_tf32(p0.y * inv);
        dst[2] = rna_tf32(p1.x * inv); dst[3] = rna_tf32(p1.y * inv);
    }
}

// ---------------- LayerNorm (writes fp32 hln + tf32-rounded copy) --------------
__global__ __launch_bounds__(256)
void ln_kernel(const float* __restrict__ g, const float* __restrict__ bb,
               float* __restrict__ hlnr) {
    __shared__ float xrow[Cn];
    __shared__ float rbuf[16];
    int tok = blockIdx.x, tid = threadIdx.x;
    int b = tok >> 11;
    int sel = g_selmap[tok];
    float s = 0.f, s2 = 0.f;
    for (int c = tid; c < Cn; c += 256) {
        float v = g_hrnn[(size_t)tok*Cn + c];
        if (sel >= 0) v += g_weighted[((size_t)(b*KSEL + sel))*Cn + c];
        xrow[c] = v; s += v; s2 += v*v;
    }
#pragma unroll
    for (int off = 16; off > 0; off >>= 1) {
        s  += __shfl_xor_sync(0xffffffffu, s, off);
        s2 += __shfl_xor_sync(0xffffffffu, s2, off);
    }
    int w = tid >> 5;
    if ((tid & 31) == 0) { rbuf[w] = s; rbuf[8 + w] = s2; }
    __syncthreads();
    if (tid == 0) {
        float S = 0.f, S2 = 0.f;
        for (int i = 0; i < 8; i++) { S += rbuf[i]; S2 += rbuf[8 + i]; }
        float mu = S / (float)Cn;
        float var = S2 / (float)Cn - mu*mu;
        rbuf[0] = mu; rbuf[1] = rsqrtf(var + 1e-5f);
    }
    __syncthreads();
    float mu = rbuf[0], inv = rbuf[1];
    for (int c = tid; c < Cn; c += 256) {
        float v = (xrow[c] - mu) * inv * g[c] + bb[c];
        g_hln[(size_t)tok*Cn + c] = v;
        hlnr[(size_t)tok*Cn + c] = rna_tf32(v);
    }
}

// ---------------- finalize ------------------------------------------------------
__global__ void finalize_kernel(float* out) {
    out[(size_t)BT*Cn + BT] = (float)g_active;
}

// ---------------- launcher ------------------------------------------------------
extern "C" void kernel_launch(void* const* d_in, const int* in_sizes, int n_in,
                              void* d_out, int out_size) {
    const float* x      = (const float*)d_in[0];
    const float* W_ih   = (const float*)d_in[1];
    const float* W_hh   = (const float*)d_in[2];
    const float* b_ih   = (const float*)d_in[3];
    const float* b_hh   = (const float*)d_in[4];
    const float* gate_w1= (const float*)d_in[5];
    const float* gate_b1= (const float*)d_in[6];
    const float* gate_w2= (const float*)d_in[7];
    const float* gate_b2= (const float*)d_in[8];
    const float* qkv_w  = (const float*)d_in[9];
    const float* qkv_b  = (const float*)d_in[10];
    const float* proj_w = (const float*)d_in[11];
    const float* proj_b = (const float*)d_in[12];
    const float* ln_g   = (const float*)d_in[13];
    const float* ln_b   = (const float*)d_in[14];
    const float* ffn_w1 = (const float*)d_in[15];
    const float* ffn_b1 = (const float*)d_in[16];
    const float* ffn_w2 = (const float*)d_in[17];
    const float* ffn_b2 = (const float*)d_in[18];
    float* out = (float*)d_out;

    float *p_xi, *p_xsel, *p_qkv, *p_y, *p_weighted, *p_hln, *p_mid, *p_wscr;
    cudaGetSymbolAddress((void**)&p_xi,       g_xi);
    cudaGetSymbolAddress((void**)&p_xsel,     g_xsel);
    cudaGetSymbolAddress((void**)&p_qkv,      g_qkv);
    cudaGetSymbolAddress((void**)&p_y,        g_y);
    cudaGetSymbolAddress((void**)&p_weighted, g_weighted);
    cudaGetSymbolAddress((void**)&p_hln,      g_hln);
    cudaGetSymbolAddress((void**)&p_mid,      g_mid);
    cudaGetSymbolAddress((void**)&p_wscr,     g_wscr);
    float* p_gsel; cudaGetSymbolAddress((void**)&p_gsel, g_gsel);
    float* p_energy_out = out + (size_t)BT*Cn;
    float* p_hlnr = p_xi;   // reuse xi scratch (free after GRU)

    const int ATTN_SMEM = (3*64*65 + 64*64) * 4;
    cudaFuncSetAttribute(attn_kernel, cudaFuncAttributeMaxDynamicSharedMemorySize, ATTN_SMEM);
    cudaFuncSetAttribute(gemm_tc_kernel<0>, cudaFuncAttributeMaxDynamicSharedMemorySize, GSM_BYTES);
    cudaFuncSetAttribute(gemm_tc_kernel<1>, cudaFuncAttributeMaxDynamicSharedMemorySize, GSM_BYTES);
    cudaFuncSetAttribute(gemm_tc_kernel<2>, cudaFuncAttributeMaxDynamicSharedMemorySize, GSM_BYTES);
    cudaFuncSetAttribute(gemm_tc_kernel<3>, cudaFuncAttributeMaxDynamicSharedMemorySize, GSM_BYTES);

    // 0) init
    init_kernel<<<64, 256>>>();

    // 1) round weights to tf32 (rna) into scratch
    cvtw_kernel<<<(WTOTAL + 255)/256, 256>>>(qkv_w, proj_w, ffn_w1, ffn_w2);

    // 2) xi = x @ W_ih^T + b_ih  (fp32 FFMA2)
    gemm_kernel<<<dim3(G3C/128, BT/128), 256>>>(x, W_ih, b_ih, p_xi, BT, G3C, Cn);

    // 3) GRU scan
    gru_kernel<<<NCTA_GRU, 192>>>(p_xi, W_hh, b_hh);

    // 4) energy
    energy_kernel<<<BT, 128>>>(gate_w1, gate_b1, gate_w2, gate_b2, p_energy_out);

    // 5) top-k
    topk_kernel<<<Bn, 1024>>>();

    // 6) gather (rounds xsel)
    gather_kernel<<<BKn, 192>>>();

    // 7) qkv GEMM
    gemm_tc_kernel<0><<<dim3(G3C/128, BKn/128), 256, GSM_BYTES>>>(
        p_xsel, p_wscr + WOFF_QKV, qkv_b, nullptr, p_qkv, BKn, G3C, Cn);

    // 8) attention (rounds y)
    attn_kernel<<<dim3(KSEL/64, Bn*Hn), 256, ATTN_SMEM>>>();

    // 9) proj GEMM (row-scale)
    gemm_tc_kernel<2><<<dim3(Cn/128, BKn/128), 256, GSM_BYTES>>>(
        p_y, p_wscr + WOFF_PROJ, proj_b, p_gsel, p_weighted, BKn, Cn, Cn);

    // 10) LayerNorm
    ln_kernel<<<BT, 256>>>(ln_g, ln_b, p_hlnr);

    // 11) ffn1 GEMM (gelu, rounded output)
    gemm_tc_kernel<1><<<dim3(DFF/128, BT/128), 256, GSM_BYTES>>>(
        p_hlnr, p_wscr + WOFF_FFN1, ffn_b1, nullptr, p_mid, BT, DFF, Cn);

    // 12) ffn2 GEMM (residual) -> out
    gemm_tc_kernel<3><<<dim3(Cn/128, BT/128), 256, GSM_BYTES>>>(
        p_mid, p_wscr + WOFF_FFN2, ffn_b2, p_hln, out, BT, Cn, DFF);

    // 13) active count
    finalize_kernel<<<1, 1>>>(out);

    (void)in_sizes; (void)n_in; (void)out_size;
}